// round 2
// baseline (speedup 1.0000x reference)
#include <cuda_runtime.h>
#include <cstdint>

// ---- problem constants (fixed by the dataset) ----
#define NND   16384      // nodes = B*S*NN
#define EDG   262144     // edges
#define DD    128        // hidden dim
#define SS    128        // seq len
#define NNPG  64         // nodes per graph-step
#define LL    6          // layers

// ---- scratch (device globals; no allocation allowed) ----
__device__ float g_h[NND * DD];                 // 8 MB   hidden state
__device__ float g_qkvs[(size_t)NND * 4 * DD];  // 32 MB  q|k|v|xr per node
__device__ int   g_deg[NND];
__device__ int   g_off[NND + 1];
__device__ int   g_cur[NND];
__device__ int   g_csr[EDG];                    // src id per CSR slot (grouped by dst)

// =====================================================================
// CSR build
// =====================================================================
__global__ void k_zero_deg() {
    int i = blockIdx.x * blockDim.x + threadIdx.x;
    if (i < NND) g_deg[i] = 0;
}

__global__ void k_count(const int* __restrict__ dst) {
    int e = blockIdx.x * blockDim.x + threadIdx.x;
    if (e < EDG) atomicAdd(&g_deg[dst[e]], 1);
}

__global__ void k_scan() {
    __shared__ int part[512];
    int t = threadIdx.x;
    int base = t * 32;
    int s = 0;
#pragma unroll
    for (int i = 0; i < 32; i++) s += g_deg[base + i];
    part[t] = s;
    __syncthreads();
    for (int ofs = 1; ofs < 512; ofs <<= 1) {
        int v = (t >= ofs) ? part[t - ofs] : 0;
        __syncthreads();
        part[t] += v;
        __syncthreads();
    }
    int run = (t == 0) ? 0 : part[t - 1];
#pragma unroll
    for (int i = 0; i < 32; i++) {
        g_off[base + i] = run;
        g_cur[base + i] = run;
        run += g_deg[base + i];
    }
    if (t == 511) g_off[NND] = part[511];
}

__global__ void k_fill(const int* __restrict__ src, const int* __restrict__ dst) {
    int e = blockIdx.x * blockDim.x + threadIdx.x;
    if (e < EDG) {
        int d = dst[e];
        int p = atomicAdd(&g_cur[d], 1);
        g_csr[p] = src[e];
    }
}

// =====================================================================
// Input projection + positional encoding: h = x @ Win + bin + pe[s]
// =====================================================================
__global__ void k_input(const float* __restrict__ x, const float* __restrict__ Win,
                        const float* __restrict__ bin, const float* __restrict__ pe) {
    int idx = blockIdx.x * blockDim.x + threadIdx.x;
    if (idx >= NND * DD) return;
    int n = idx >> 7;
    int d = idx & 127;
    int s = (n / NNPG) % SS;
    float acc = bin[d] + pe[s * DD + d];
    const float* xr = x + n * 9;
#pragma unroll
    for (int f = 0; f < 9; f++) acc = fmaf(xr[f], Win[f * DD + d], acc);
    g_h[idx] = acc;
}

// =====================================================================
// Fused QKVS GEMM on tensor cores: mma.sync m16n8k8 tf32
// grid = (NND/128, 4mat). Block 256 thr = 8 warps.
// Warp w: rowgroup rg=w>>1 (32 rows: 2 m16 tiles), colgroup cg=w&1 (64 cols: 8 n8 tiles)
// B (weights) staged in smem pre-swizzled to fragment order, in 2 K-halves.
// =====================================================================
__device__ __forceinline__ uint32_t f2tf32(float f) {
    uint32_t r;
    asm("cvt.rna.tf32.f32 %0, %1;" : "=r"(r) : "f"(f));
    return r;
}

__device__ __forceinline__ void mma_tf32(float* d, const uint32_t* a, const uint32_t* b) {
    asm("mma.sync.aligned.m16n8k8.row.col.f32.tf32.tf32.f32 "
        "{%0,%1,%2,%3}, {%4,%5,%6,%7}, {%8,%9}, {%0,%1,%2,%3};"
        : "+f"(d[0]), "+f"(d[1]), "+f"(d[2]), "+f"(d[3])
        : "r"(a[0]), "r"(a[1]), "r"(a[2]), "r"(a[3]), "r"(b[0]), "r"(b[1]));
}

__global__ __launch_bounds__(256) void k_gemm(
    const float* __restrict__ Wq, const float* __restrict__ Wk,
    const float* __restrict__ Wv, const float* __restrict__ Ws,
    const float* __restrict__ bq, const float* __restrict__ bk,
    const float* __restrict__ bv, const float* __restrict__ bs)
{
    // fragment-order B tiles for 8 k-steps: [ks][ntile16][lane32][reg2]
    __shared__ uint32_t sB[8 * 16 * 32 * 2];   // 32 KB

    int mat  = blockIdx.y;
    int row0 = blockIdx.x * 128;
    const float* W    = (mat == 0) ? Wq : (mat == 1) ? Wk : (mat == 2) ? Wv : Ws;
    const float* bias = (mat == 0) ? bq : (mat == 1) ? bk : (mat == 2) ? bv : bs;

    int tid  = threadIdx.x;
    int lane = tid & 31;
    int wid  = tid >> 5;
    int rg   = wid >> 1;           // 0..3
    int cg   = wid & 1;            // 0..1
    int gid  = lane >> 2;          // 0..7
    int tig  = lane & 3;           // 0..3

    float acc[2][8][4];
#pragma unroll
    for (int rt = 0; rt < 2; rt++)
#pragma unroll
        for (int nt = 0; nt < 8; nt++)
#pragma unroll
            for (int c = 0; c < 4; c++) acc[rt][nt][c] = 0.f;

    for (int half = 0; half < 2; half++) {
        // stage 64 k-rows of W into fragment order
        __syncthreads();
        for (int e = tid; e < 8192; e += 256) {
            int kk = e >> 7;          // 0..63
            int n  = e & 127;
            float w = W[(size_t)(half * 64 + kk) * 128 + n];
            int ksl = kk >> 3, kin = kk & 7;
            int l = (n & 7) * 4 + (kin & 3);
            int nt = n >> 3;
            sB[((((ksl * 16 + nt) * 32 + l) << 1) | (kin >> 2))] = f2tf32(w);
        }
        __syncthreads();

#pragma unroll
        for (int ks = 0; ks < 8; ks++) {
            uint32_t a[2][4];
#pragma unroll
            for (int rt = 0; rt < 2; rt++) {
                const float* ap = g_h + (size_t)(row0 + rg * 32 + rt * 16 + gid) * 128
                                + half * 64 + ks * 8 + tig;
                a[rt][0] = f2tf32(__ldg(ap));
                a[rt][2] = f2tf32(__ldg(ap + 4));
                a[rt][1] = f2tf32(__ldg(ap + 8 * 128));
                a[rt][3] = f2tf32(__ldg(ap + 8 * 128 + 4));
            }
#pragma unroll
            for (int nt = 0; nt < 8; nt++) {
                const uint32_t* bp = &sB[(((ks * 16 + cg * 8 + nt) * 32 + lane) << 1)];
                uint32_t b[2] = {bp[0], bp[1]};
                mma_tf32(acc[0][nt], a[0], b);
                mma_tf32(acc[1][nt], a[1], b);
            }
        }
    }

    // epilogue: bias + store (float2 per c0/c1 pair)
#pragma unroll
    for (int nt = 0; nt < 8; nt++) {
        int c = cg * 64 + nt * 8 + tig * 2;
        float b0 = bias[c], b1 = bias[c + 1];
#pragma unroll
        for (int rt = 0; rt < 2; rt++) {
            int r = row0 + rg * 32 + rt * 16 + gid;
            float* o0 = g_qkvs + (size_t)r * 512 + mat * 128 + c;
            float* o1 = g_qkvs + (size_t)(r + 8) * 512 + mat * 128 + c;
            float2 v0 = make_float2(acc[rt][nt][0] + b0, acc[rt][nt][1] + b1);
            float2 v1 = make_float2(acc[rt][nt][2] + b0, acc[rt][nt][3] + b1);
            *(float2*)o0 = v0;
            *(float2*)o1 = v1;
        }
    }
}

// =====================================================================
// Fused attention: one warp per dst node. lane = eq*8 + head
// (4 edges in flight x 8 heads; each lane does a full 16-dim head dot ->
//  no shuffles in the edge loop). softmax is shift-invariant so no
//  running max is needed (scores are tiny with 0.02-scale weights).
// =====================================================================
__global__ __launch_bounds__(256) void k_attn(
    const float* __restrict__ Wb, const float* __restrict__ bb,
    const float* __restrict__ lng, const float* __restrict__ lnb)
{
    __shared__ float sAgg[8][136];   // per warp: 128 agg + 8 den

    int gw = (blockIdx.x * 256 + threadIdx.x) >> 5;   // node id
    if (gw >= NND) return;
    int lane = threadIdx.x & 31;
    int warp = (threadIdx.x >> 5);
    int hh = lane & 7;    // head
    int eq = lane >> 3;   // edge slot

    // q for head hh (16 dims), pre-scaled by 1/sqrt(16)
    float4 q0, q1, q2, q3;
    {
        const float4* qp = (const float4*)(g_qkvs + (size_t)gw * 512 + hh * 16);
        q0 = qp[0]; q1 = qp[1]; q2 = qp[2]; q3 = qp[3];
        q0.x *= .25f; q0.y *= .25f; q0.z *= .25f; q0.w *= .25f;
        q1.x *= .25f; q1.y *= .25f; q1.z *= .25f; q1.w *= .25f;
        q2.x *= .25f; q2.y *= .25f; q2.z *= .25f; q2.w *= .25f;
        q3.x *= .25f; q3.y *= .25f; q3.z *= .25f; q3.w *= .25f;
    }

    float acc[16];
#pragma unroll
    for (int j = 0; j < 16; j++) acc[j] = 0.f;
    float den = 0.f;

    int beg = g_off[gw], end = g_off[gw + 1];
    for (int e0 = beg; e0 < end; e0 += 4) {
        int e = e0 + eq;
        bool act = e < end;
        int s = g_csr[act ? e : beg];
        const float4* kp = (const float4*)(g_qkvs + (size_t)s * 512 + 128 + hh * 16);
        const float4* vp = (const float4*)(g_qkvs + (size_t)s * 512 + 256 + hh * 16);
        float4 ka = kp[0], kb = kp[1], kc = kp[2], kd = kp[3];
        float sc = q0.x * ka.x + q0.y * ka.y + q0.z * ka.z + q0.w * ka.w
                 + q1.x * kb.x + q1.y * kb.y + q1.z * kb.z + q1.w * kb.w
                 + q2.x * kc.x + q2.y * kc.y + q2.z * kc.z + q2.w * kc.w
                 + q3.x * kd.x + q3.y * kd.y + q3.z * kd.z + q3.w * kd.w;
        float p = act ? __expf(sc) : 0.f;
        float4 va = vp[0], vb = vp[1], vc = vp[2], vd = vp[3];
        acc[0]  += p * va.x; acc[1]  += p * va.y; acc[2]  += p * va.z; acc[3]  += p * va.w;
        acc[4]  += p * vb.x; acc[5]  += p * vb.y; acc[6]  += p * vb.z; acc[7]  += p * vb.w;
        acc[8]  += p * vc.x; acc[9]  += p * vc.y; acc[10] += p * vc.z; acc[11] += p * vc.w;
        acc[12] += p * vd.x; acc[13] += p * vd.y; acc[14] += p * vd.z; acc[15] += p * vd.w;
        den += p;
    }

    // reduce over the 4 edge slots (lanes differing in bits 3,4)
#pragma unroll
    for (int j = 0; j < 16; j++) {
        acc[j] += __shfl_xor_sync(0xffffffffu, acc[j], 8);
        acc[j] += __shfl_xor_sync(0xffffffffu, acc[j], 16);
    }
    den += __shfl_xor_sync(0xffffffffu, den, 8);
    den += __shfl_xor_sync(0xffffffffu, den, 16);

    if (eq == 0) {
#pragma unroll
        for (int j = 0; j < 16; j++) sAgg[warp][hh * 16 + j] = acc[j];
        sAgg[warp][128 + hh] = den;
    }
    __syncwarp();

    int d0 = lane * 4;
    float inv = 1.f / (sAgg[warp][128 + (lane >> 2)] + 1e-16f);
    float ag[4];
#pragma unroll
    for (int j = 0; j < 4; j++) ag[j] = sAgg[warp][d0 + j] * inv;

    // beta gate: sigmoid([agg, xr, agg-xr] @ Wb + bb)
    float4 xr = ((const float4*)(g_qkvs + (size_t)gw * 512 + 384))[lane];
    float xrv[4] = {xr.x, xr.y, xr.z, xr.w};
    float part = 0.f;
#pragma unroll
    for (int j = 0; j < 4; j++) {
        int d = d0 + j;
        part += ag[j] * Wb[d] + xrv[j] * Wb[128 + d] + (ag[j] - xrv[j]) * Wb[256 + d];
    }
#pragma unroll
    for (int o = 16; o; o >>= 1) part += __shfl_xor_sync(0xffffffffu, part, o);
    float beta = 1.f / (1.f + __expf(-(part + bb[0])));

    // hn = beta*xr + (1-beta)*agg ; h = LN(h + hn)
    float4 hold = ((const float4*)(g_h + (size_t)gw * 128))[lane];
    float hv[4] = {hold.x, hold.y, hold.z, hold.w};
    float y[4];
#pragma unroll
    for (int j = 0; j < 4; j++)
        y[j] = hv[j] + beta * xrv[j] + (1.f - beta) * ag[j];

    float ssum = y[0] + y[1] + y[2] + y[3];
#pragma unroll
    for (int o = 16; o; o >>= 1) ssum += __shfl_xor_sync(0xffffffffu, ssum, o);
    float mean = ssum * (1.f / 128.f);

    float vs = 0.f;
#pragma unroll
    for (int j = 0; j < 4; j++) { float t = y[j] - mean; vs += t * t; }
#pragma unroll
    for (int o = 16; o; o >>= 1) vs += __shfl_xor_sync(0xffffffffu, vs, o);
    float rstd = rsqrtf(vs * (1.f / 128.f) + 1e-5f);

    float4 outv;
    outv.x = (y[0] - mean) * rstd * lng[d0 + 0] + lnb[d0 + 0];
    outv.y = (y[1] - mean) * rstd * lng[d0 + 1] + lnb[d0 + 1];
    outv.z = (y[2] - mean) * rstd * lng[d0 + 2] + lnb[d0 + 2];
    outv.w = (y[3] - mean) * rstd * lng[d0 + 3] + lnb[d0 + 3];
    ((float4*)(g_h + (size_t)gw * 128))[lane] = outv;
}

// =====================================================================
// Output head: out = relu(h @ Wo1 + bo1) @ Wo2 + bo2    (16 nodes / block)
// =====================================================================
__global__ __launch_bounds__(256) void k_out(
    const float* __restrict__ Wo1, const float* __restrict__ bo1,
    const float* __restrict__ Wo2, const float* __restrict__ bo2,
    float* __restrict__ out)
{
    __shared__ float w1[128 * 64];   // 32 KB
    __shared__ float hs[16][128];    //  8 KB
    __shared__ float ts[16][64];     //  4 KB
    int tid = threadIdx.x;
    int n0 = blockIdx.x * 16;

    for (int i = tid; i < 128 * 64 / 4; i += 256)
        ((float4*)w1)[i] = ((const float4*)Wo1)[i];
    for (int i = tid; i < 16 * 128 / 4; i += 256)
        ((float4*)&hs[0][0])[i] = ((const float4*)(g_h + (size_t)n0 * 128))[i];
    __syncthreads();

    int j = tid & 63, g0 = tid >> 6;
    float a0 = bo1[j], a1 = a0, a2 = a0, a3 = a0;
#pragma unroll 8
    for (int d = 0; d < 128; d++) {
        float w = w1[d * 64 + j];
        a0 = fmaf(hs[g0 +  0][d], w, a0);
        a1 = fmaf(hs[g0 +  4][d], w, a1);
        a2 = fmaf(hs[g0 +  8][d], w, a2);
        a3 = fmaf(hs[g0 + 12][d], w, a3);
    }
    ts[g0 +  0][j] = fmaxf(a0, 0.f);
    ts[g0 +  4][j] = fmaxf(a1, 0.f);
    ts[g0 +  8][j] = fmaxf(a2, 0.f);
    ts[g0 + 12][j] = fmaxf(a3, 0.f);
    __syncthreads();

    if (tid < 48) {
        int n = tid / 3, c = tid % 3;
        float o = bo2[c];
#pragma unroll
        for (int k = 0; k < 64; k++) o = fmaf(ts[n][k], Wo2[k * 3 + c], o);
        out[(size_t)(n0 + n) * 3 + c] = o;
    }
}

// =====================================================================
// launcher
// =====================================================================
extern "C" void kernel_launch(void* const* d_in, const int* in_sizes, int n_in,
                              void* d_out, int out_size)
{
    const float* x    = (const float*)d_in[0];
    const int*   ei   = (const int*)  d_in[1];
    const float* pe   = (const float*)d_in[2];
    const float* Win  = (const float*)d_in[3];
    const float* bin  = (const float*)d_in[4];
    const float* Wq   = (const float*)d_in[5];
    const float* bq   = (const float*)d_in[6];
    const float* Wk   = (const float*)d_in[7];
    const float* bk   = (const float*)d_in[8];
    const float* Wv   = (const float*)d_in[9];
    const float* bv   = (const float*)d_in[10];
    const float* Ws   = (const float*)d_in[11];
    const float* bs   = (const float*)d_in[12];
    const float* Wb   = (const float*)d_in[13];
    const float* bb   = (const float*)d_in[14];
    const float* lng  = (const float*)d_in[15];
    const float* lnb  = (const float*)d_in[16];
    const float* Wo1  = (const float*)d_in[17];
    const float* bo1  = (const float*)d_in[18];
    const float* Wo2  = (const float*)d_in[19];
    const float* bo2  = (const float*)d_in[20];
    float* out = (float*)d_out;

    const int* src = ei;
    const int* dst = ei + EDG;

    k_zero_deg<<<NND / 256, 256>>>();
    k_count<<<EDG / 256, 256>>>(dst);
    k_scan<<<1, 512>>>();
    k_fill<<<EDG / 256, 256>>>(src, dst);

    k_input<<<NND * DD / 256, 256>>>(x, Win, bin, pe);

    for (int l = 0; l < LL; l++) {
        dim3 gg(NND / 128, 4);
        k_gemm<<<gg, 256>>>(Wq + (size_t)l * DD * DD, Wk + (size_t)l * DD * DD,
                            Wv + (size_t)l * DD * DD, Ws + (size_t)l * DD * DD,
                            bq + l * DD, bk + l * DD, bv + l * DD, bs + l * DD);
        k_attn<<<NND / 8, 256>>>(Wb + l * 384, bb + l, lng + l * DD, lnb + l * DD);
    }

    k_out<<<NND / 16, 256>>>(Wo1, bo1, Wo2, bo2, out);
}

// round 3
// speedup vs baseline: 1.2894x; 1.2894x over previous
#include <cuda_runtime.h>
#include <cstdint>

// ---- problem constants (fixed by the dataset) ----
#define NND   16384      // nodes = B*S*NN
#define EDG   262144     // edges
#define DD    128        // hidden dim
#define SS    128        // seq len
#define NNPG  64         // nodes per graph-step
#define LL    6          // layers

// ---- scratch (device globals; no allocation allowed) ----
__device__ float g_h[NND * DD];                 // 8 MB   hidden state
__device__ float g_qkvs[(size_t)NND * 4 * DD];  // 32 MB  q|k|v|xr per node
__device__ int   g_deg[NND];
__device__ int   g_off[NND + 1];
__device__ int   g_cur[NND];
__device__ int   g_csr[EDG];                    // src id per CSR slot (grouped by dst)

// =====================================================================
// CSR build
// =====================================================================
__global__ void k_zero_deg() {
    int i = blockIdx.x * blockDim.x + threadIdx.x;
    if (i < NND) g_deg[i] = 0;
}

__global__ void k_count(const int* __restrict__ dst) {
    int e = blockIdx.x * blockDim.x + threadIdx.x;
    if (e < EDG) atomicAdd(&g_deg[dst[e]], 1);
}

__global__ void k_scan() {
    __shared__ int part[512];
    int t = threadIdx.x;
    int base = t * 32;
    int s = 0;
#pragma unroll
    for (int i = 0; i < 32; i++) s += g_deg[base + i];
    part[t] = s;
    __syncthreads();
    for (int ofs = 1; ofs < 512; ofs <<= 1) {
        int v = (t >= ofs) ? part[t - ofs] : 0;
        __syncthreads();
        part[t] += v;
        __syncthreads();
    }
    int run = (t == 0) ? 0 : part[t - 1];
#pragma unroll
    for (int i = 0; i < 32; i++) {
        g_off[base + i] = run;
        g_cur[base + i] = run;
        run += g_deg[base + i];
    }
    if (t == 511) g_off[NND] = part[511];
}

__global__ void k_fill(const int* __restrict__ src, const int* __restrict__ dst) {
    int e = blockIdx.x * blockDim.x + threadIdx.x;
    if (e < EDG) {
        int d = dst[e];
        int p = atomicAdd(&g_cur[d], 1);
        g_csr[p] = src[e];
    }
}

// =====================================================================
// Input projection + positional encoding: h = x @ Win + bin + pe[s]
// =====================================================================
__global__ void k_input(const float* __restrict__ x, const float* __restrict__ Win,
                        const float* __restrict__ bin, const float* __restrict__ pe) {
    int idx = blockIdx.x * blockDim.x + threadIdx.x;
    if (idx >= NND * DD) return;
    int n = idx >> 7;
    int d = idx & 127;
    int s = (n / NNPG) % SS;
    float acc = bin[d] + pe[s * DD + d];
    const float* xr = x + n * 9;
#pragma unroll
    for (int f = 0; f < 9; f++) acc = fmaf(xr[f], Win[f * DD + d], acc);
    g_h[idx] = acc;
}

// =====================================================================
// Fused QKVS GEMM on tensor cores: mma.sync m16n8k8 tf32
// =====================================================================
__device__ __forceinline__ uint32_t f2tf32(float f) {
    uint32_t r;
    asm("cvt.rna.tf32.f32 %0, %1;" : "=r"(r) : "f"(f));
    return r;
}

__device__ __forceinline__ void mma_tf32(float* d, const uint32_t* a, const uint32_t* b) {
    asm("mma.sync.aligned.m16n8k8.row.col.f32.tf32.tf32.f32 "
        "{%0,%1,%2,%3}, {%4,%5,%6,%7}, {%8,%9}, {%0,%1,%2,%3};"
        : "+f"(d[0]), "+f"(d[1]), "+f"(d[2]), "+f"(d[3])
        : "r"(a[0]), "r"(a[1]), "r"(a[2]), "r"(a[3]), "r"(b[0]), "r"(b[1]));
}

__global__ __launch_bounds__(256) void k_gemm(
    const float* __restrict__ Wq, const float* __restrict__ Wk,
    const float* __restrict__ Wv, const float* __restrict__ Ws,
    const float* __restrict__ bq, const float* __restrict__ bk,
    const float* __restrict__ bv, const float* __restrict__ bs)
{
    __shared__ uint32_t sB[8 * 16 * 32 * 2];   // 32 KB fragment-order B

    int mat  = blockIdx.y;
    int row0 = blockIdx.x * 128;
    const float* W    = (mat == 0) ? Wq : (mat == 1) ? Wk : (mat == 2) ? Wv : Ws;
    const float* bias = (mat == 0) ? bq : (mat == 1) ? bk : (mat == 2) ? bv : bs;

    int tid  = threadIdx.x;
    int lane = tid & 31;
    int wid  = tid >> 5;
    int rg   = wid >> 1;
    int cg   = wid & 1;
    int gid  = lane >> 2;
    int tig  = lane & 3;

    float acc[2][8][4];
#pragma unroll
    for (int rt = 0; rt < 2; rt++)
#pragma unroll
        for (int nt = 0; nt < 8; nt++)
#pragma unroll
            for (int c = 0; c < 4; c++) acc[rt][nt][c] = 0.f;

    for (int half = 0; half < 2; half++) {
        __syncthreads();
        for (int e = tid; e < 8192; e += 256) {
            int kk = e >> 7;
            int n  = e & 127;
            float w = W[(size_t)(half * 64 + kk) * 128 + n];
            int ksl = kk >> 3, kin = kk & 7;
            int l = (n & 7) * 4 + (kin & 3);
            int nt = n >> 3;
            sB[((((ksl * 16 + nt) * 32 + l) << 1) | (kin >> 2))] = f2tf32(w);
        }
        __syncthreads();

#pragma unroll
        for (int ks = 0; ks < 8; ks++) {
            uint32_t a[2][4];
#pragma unroll
            for (int rt = 0; rt < 2; rt++) {
                const float* ap = g_h + (size_t)(row0 + rg * 32 + rt * 16 + gid) * 128
                                + half * 64 + ks * 8 + tig;
                a[rt][0] = f2tf32(__ldg(ap));
                a[rt][2] = f2tf32(__ldg(ap + 4));
                a[rt][1] = f2tf32(__ldg(ap + 8 * 128));
                a[rt][3] = f2tf32(__ldg(ap + 8 * 128 + 4));
            }
#pragma unroll
            for (int nt = 0; nt < 8; nt++) {
                const uint32_t* bp = &sB[(((ks * 16 + cg * 8 + nt) * 32 + lane) << 1)];
                uint32_t b[2] = {bp[0], bp[1]};
                mma_tf32(acc[0][nt], a[0], b);
                mma_tf32(acc[1][nt], a[1], b);
            }
        }
    }

#pragma unroll
    for (int nt = 0; nt < 8; nt++) {
        int c = cg * 64 + nt * 8 + tig * 2;
        float b0 = bias[c], b1 = bias[c + 1];
#pragma unroll
        for (int rt = 0; rt < 2; rt++) {
            int r = row0 + rg * 32 + rt * 16 + gid;
            float* o0 = g_qkvs + (size_t)r * 512 + mat * 128 + c;
            float* o1 = g_qkvs + (size_t)(r + 8) * 512 + mat * 128 + c;
            *(float2*)o0 = make_float2(acc[rt][nt][0] + b0, acc[rt][nt][1] + b1);
            *(float2*)o1 = make_float2(acc[rt][nt][2] + b0, acc[rt][nt][3] + b1);
        }
    }
}

// =====================================================================
// Fused attention: one warp per dst node.
// lane = eq*16 + t (2 edges in flight, 16 lanes each).
// Lane reads contiguous float4s -> every LDG.128 touches each 128B line
// exactly once (8 wavefronts/edge, the minimum). CSR ids prefetched 32
// at a time and distributed via shfl (no per-edge index dependency).
// Shift-invariant softmax (scores tiny; no running max needed).
// =====================================================================
__global__ __launch_bounds__(256) void k_attn(
    const float* __restrict__ Wb, const float* __restrict__ bb,
    const float* __restrict__ lng, const float* __restrict__ lnb)
{
    int gw = (blockIdx.x * 256 + threadIdx.x) >> 5;   // node id
    if (gw >= NND) return;
    int lane = threadIdx.x & 31;
    int t  = lane & 15;          // 16-lane slot within edge
    int eq = lane >> 4;          // edge slot (0/1)

    const float* qrow = g_qkvs + (size_t)gw * 512;
    float4 q1 = ((const float4*)qrow)[t];        // dims t*4..t*4+3   (head t>>2)
    float4 q2 = ((const float4*)qrow)[16 + t];   // dims 64+t*4..     (head 4+(t>>2))
    q1.x *= .25f; q1.y *= .25f; q1.z *= .25f; q1.w *= .25f;
    q2.x *= .25f; q2.y *= .25f; q2.z *= .25f; q2.w *= .25f;

    float ac1[4] = {0.f, 0.f, 0.f, 0.f};
    float ac2[4] = {0.f, 0.f, 0.f, 0.f};
    float den1 = 0.f, den2 = 0.f;

    int beg = g_off[gw], end = g_off[gw + 1];
    for (int base = beg; base < end; base += 32) {
        int cnt = min(32, end - base);
        int id = (base + lane < end) ? g_csr[base + lane] : 0;
#pragma unroll 2
        for (int e = 0; e < cnt; e += 2) {
            int ee = e + eq;
            bool act = ee < cnt;
            int s = __shfl_sync(0xffffffffu, id, ee & 31);
            const float4* krow = (const float4*)(g_qkvs + (size_t)s * 512 + 128);
            const float4* vrow = (const float4*)(g_qkvs + (size_t)s * 512 + 256);
            float4 k1 = krow[t];
            float4 k2 = krow[16 + t];
            float4 v1 = vrow[t];
            float4 v2 = vrow[16 + t];
            float d1 = q1.x * k1.x + q1.y * k1.y + q1.z * k1.z + q1.w * k1.w;
            float d2 = q2.x * k2.x + q2.y * k2.y + q2.z * k2.z + q2.w * k2.w;
            // reduce partial dots within each 4-lane head group
            d1 += __shfl_xor_sync(0xffffffffu, d1, 1);
            d2 += __shfl_xor_sync(0xffffffffu, d2, 1);
            d1 += __shfl_xor_sync(0xffffffffu, d1, 2);
            d2 += __shfl_xor_sync(0xffffffffu, d2, 2);
            // exp dedup: even lanes exp(d1), odd lanes exp(d2), butterfly
            float scsel = (lane & 1) ? d2 : d1;
            float p = act ? __expf(scsel) : 0.f;
            float po = __shfl_xor_sync(0xffffffffu, p, 1);
            float p1 = (lane & 1) ? po : p;
            float p2 = (lane & 1) ? p : po;
            ac1[0] += p1 * v1.x; ac1[1] += p1 * v1.y;
            ac1[2] += p1 * v1.z; ac1[3] += p1 * v1.w;
            ac2[0] += p2 * v2.x; ac2[1] += p2 * v2.y;
            ac2[2] += p2 * v2.z; ac2[3] += p2 * v2.w;
            den1 += p1; den2 += p2;
        }
    }

    // reduce across the two edge slots (xor bit 4)
#pragma unroll
    for (int j = 0; j < 4; j++) {
        ac1[j] += __shfl_xor_sync(0xffffffffu, ac1[j], 16);
        ac2[j] += __shfl_xor_sync(0xffffffffu, ac2[j], 16);
    }
    den1 += __shfl_xor_sync(0xffffffffu, den1, 16);
    den2 += __shfl_xor_sync(0xffffffffu, den2, 16);

    float inv1 = 1.f / (den1 + 1e-16f);
    float inv2 = 1.f / (den2 + 1e-16f);
    float ag1[4], ag2[4];
#pragma unroll
    for (int j = 0; j < 4; j++) { ag1[j] = ac1[j] * inv1; ag2[j] = ac2[j] * inv2; }

    // lane owns dims dA = t*4.. and dB = 64+t*4.. (duplicated across eq)
    int dA = t * 4, dB = 64 + t * 4;
    float4 xa = ((const float4*)(qrow + 384))[t];
    float4 xb = ((const float4*)(qrow + 384))[16 + t];
    float xrA[4] = {xa.x, xa.y, xa.z, xa.w};
    float xrB[4] = {xb.x, xb.y, xb.z, xb.w};

    // beta gate (warp sum counts everything twice -> 0.5 factor)
    float part = 0.f;
#pragma unroll
    for (int j = 0; j < 4; j++) {
        part += ag1[j] * Wb[dA + j] + xrA[j] * Wb[128 + dA + j]
              + (ag1[j] - xrA[j]) * Wb[256 + dA + j];
        part += ag2[j] * Wb[dB + j] + xrB[j] * Wb[128 + dB + j]
              + (ag2[j] - xrB[j]) * Wb[256 + dB + j];
    }
#pragma unroll
    for (int o = 16; o; o >>= 1) part += __shfl_xor_sync(0xffffffffu, part, o);
    float beta = 1.f / (1.f + __expf(-(0.5f * part + bb[0])));

    // hn = beta*xr + (1-beta)*agg ; h = LN(h + hn)
    float4 ha = ((const float4*)(g_h + (size_t)gw * 128))[t];
    float4 hb = ((const float4*)(g_h + (size_t)gw * 128))[16 + t];
    float hvA[4] = {ha.x, ha.y, ha.z, ha.w};
    float hvB[4] = {hb.x, hb.y, hb.z, hb.w};
    float yA[4], yB[4];
#pragma unroll
    for (int j = 0; j < 4; j++) {
        yA[j] = hvA[j] + beta * xrA[j] + (1.f - beta) * ag1[j];
        yB[j] = hvB[j] + beta * xrB[j] + (1.f - beta) * ag2[j];
    }

    float ssum = yA[0] + yA[1] + yA[2] + yA[3] + yB[0] + yB[1] + yB[2] + yB[3];
#pragma unroll
    for (int o = 16; o; o >>= 1) ssum += __shfl_xor_sync(0xffffffffu, ssum, o);
    float mean = ssum * (1.f / 256.f);   // duplicated across eq -> /256

    float vs = 0.f;
#pragma unroll
    for (int j = 0; j < 4; j++) {
        float ta = yA[j] - mean; vs += ta * ta;
        float tb = yB[j] - mean; vs += tb * tb;
    }
#pragma unroll
    for (int o = 16; o; o >>= 1) vs += __shfl_xor_sync(0xffffffffu, vs, o);
    float rstd = rsqrtf(vs * (1.f / 256.f) + 1e-5f);

    if (eq == 0) {
        float4 oA, oB;
        oA.x = (yA[0] - mean) * rstd * lng[dA + 0] + lnb[dA + 0];
        oA.y = (yA[1] - mean) * rstd * lng[dA + 1] + lnb[dA + 1];
        oA.z = (yA[2] - mean) * rstd * lng[dA + 2] + lnb[dA + 2];
        oA.w = (yA[3] - mean) * rstd * lng[dA + 3] + lnb[dA + 3];
        oB.x = (yB[0] - mean) * rstd * lng[dB + 0] + lnb[dB + 0];
        oB.y = (yB[1] - mean) * rstd * lng[dB + 1] + lnb[dB + 1];
        oB.z = (yB[2] - mean) * rstd * lng[dB + 2] + lnb[dB + 2];
        oB.w = (yB[3] - mean) * rstd * lng[dB + 3] + lnb[dB + 3];
        ((float4*)(g_h + (size_t)gw * 128))[t] = oA;
        ((float4*)(g_h + (size_t)gw * 128))[16 + t] = oB;
    }
}

// =====================================================================
// Output head: out = relu(h @ Wo1 + bo1) @ Wo2 + bo2    (16 nodes / block)
// =====================================================================
__global__ __launch_bounds__(256) void k_out(
    const float* __restrict__ Wo1, const float* __restrict__ bo1,
    const float* __restrict__ Wo2, const float* __restrict__ bo2,
    float* __restrict__ out)
{
    __shared__ float w1[128 * 64];
    __shared__ float hs[16][128];
    __shared__ float ts[16][64];
    int tid = threadIdx.x;
    int n0 = blockIdx.x * 16;

    for (int i = tid; i < 128 * 64 / 4; i += 256)
        ((float4*)w1)[i] = ((const float4*)Wo1)[i];
    for (int i = tid; i < 16 * 128 / 4; i += 256)
        ((float4*)&hs[0][0])[i] = ((const float4*)(g_h + (size_t)n0 * 128))[i];
    __syncthreads();

    int j = tid & 63, g0 = tid >> 6;
    float a0 = bo1[j], a1 = a0, a2 = a0, a3 = a0;
#pragma unroll 8
    for (int d = 0; d < 128; d++) {
        float w = w1[d * 64 + j];
        a0 = fmaf(hs[g0 +  0][d], w, a0);
        a1 = fmaf(hs[g0 +  4][d], w, a1);
        a2 = fmaf(hs[g0 +  8][d], w, a2);
        a3 = fmaf(hs[g0 + 12][d], w, a3);
    }
    ts[g0 +  0][j] = fmaxf(a0, 0.f);
    ts[g0 +  4][j] = fmaxf(a1, 0.f);
    ts[g0 +  8][j] = fmaxf(a2, 0.f);
    ts[g0 + 12][j] = fmaxf(a3, 0.f);
    __syncthreads();

    if (tid < 48) {
        int n = tid / 3, c = tid % 3;
        float o = bo2[c];
#pragma unroll
        for (int k = 0; k < 64; k++) o = fmaf(ts[n][k], Wo2[k * 3 + c], o);
        out[(size_t)(n0 + n) * 3 + c] = o;
    }
}

// =====================================================================
// launcher  (order chosen so k_gemm layer0 is the 4th launch -> lands in
// ncu's captured slot, replacing k_fill in the profile)
// =====================================================================
extern "C" void kernel_launch(void* const* d_in, const int* in_sizes, int n_in,
                              void* d_out, int out_size)
{
    const float* x    = (const float*)d_in[0];
    const int*   ei   = (const int*)  d_in[1];
    const float* pe   = (const float*)d_in[2];
    const float* Win  = (const float*)d_in[3];
    const float* bin  = (const float*)d_in[4];
    const float* Wq   = (const float*)d_in[5];
    const float* bq   = (const float*)d_in[6];
    const float* Wk   = (const float*)d_in[7];
    const float* bk   = (const float*)d_in[8];
    const float* Wv   = (const float*)d_in[9];
    const float* bv   = (const float*)d_in[10];
    const float* Ws   = (const float*)d_in[11];
    const float* bs   = (const float*)d_in[12];
    const float* Wb   = (const float*)d_in[13];
    const float* bb   = (const float*)d_in[14];
    const float* lng  = (const float*)d_in[15];
    const float* lnb  = (const float*)d_in[16];
    const float* Wo1  = (const float*)d_in[17];
    const float* bo1  = (const float*)d_in[18];
    const float* Wo2  = (const float*)d_in[19];
    const float* bo2  = (const float*)d_in[20];
    float* out = (float*)d_out;

    const int* src = ei;
    const int* dst = ei + EDG;

    // 1-3: independent prep
    k_zero_deg<<<NND / 256, 256>>>();
    k_count<<<EDG / 256, 256>>>(dst);
    k_input<<<NND * DD / 256, 256>>>(x, Win, bin, pe);

    // 4: layer-0 GEMM (only depends on k_input) -> profiled slot
    dim3 gg(NND / 128, 4);
    k_gemm<<<gg, 256>>>(Wq, Wk, Wv, Ws, bq, bk, bv, bs);

    // 5-6: finish CSR
    k_scan<<<1, 512>>>();
    k_fill<<<EDG / 256, 256>>>(src, dst);

    // layer 0 attention, then remaining layers
    k_attn<<<NND / 8, 256>>>(Wb, bb, lng, lnb);
    for (int l = 1; l < LL; l++) {
        k_gemm<<<gg, 256>>>(Wq + (size_t)l * DD * DD, Wk + (size_t)l * DD * DD,
                            Wv + (size_t)l * DD * DD, Ws + (size_t)l * DD * DD,
                            bq + l * DD, bk + l * DD, bv + l * DD, bs + l * DD);
        k_attn<<<NND / 8, 256>>>(Wb + l * 384, bb + l, lng + l * DD, lnb + l * DD);
    }

    k_out<<<NND / 16, 256>>>(Wo1, bo1, Wo2, bo2, out);
}

// round 4
// speedup vs baseline: 1.5823x; 1.2272x over previous
#include <cuda_runtime.h>
#include <cstdint>

// ---- problem constants (fixed by the dataset) ----
#define NND   16384      // nodes = B*S*NN
#define EDG   262144     // edges
#define DD    128        // hidden dim
#define SS    128        // seq len
#define NNPG  64         // nodes per graph-step
#define LL    6          // layers

// ---- scratch (device globals; no allocation allowed) ----
__device__ float g_h[NND * DD];                 // 8 MB   hidden state
__device__ float g_qkvs[(size_t)NND * 4 * DD];  // 32 MB  q|k|v|xr per node
__device__ int   g_deg[NND];
__device__ int   g_off[NND + 1];
__device__ int   g_cur[NND];
__device__ int   g_csr[EDG];                    // src id per CSR slot (grouped by dst)

// =====================================================================
// CSR build
// =====================================================================
__global__ void k_zero_deg() {
    int i = blockIdx.x * blockDim.x + threadIdx.x;
    if (i < NND) g_deg[i] = 0;
}

__global__ void k_count(const int* __restrict__ dst) {
    int e = blockIdx.x * blockDim.x + threadIdx.x;
    if (e < EDG) atomicAdd(&g_deg[dst[e]], 1);
}

__global__ void k_scan() {
    __shared__ int part[512];
    int t = threadIdx.x;
    int base = t * 32;
    int s = 0;
#pragma unroll
    for (int i = 0; i < 32; i++) s += g_deg[base + i];
    part[t] = s;
    __syncthreads();
    for (int ofs = 1; ofs < 512; ofs <<= 1) {
        int v = (t >= ofs) ? part[t - ofs] : 0;
        __syncthreads();
        part[t] += v;
        __syncthreads();
    }
    int run = (t == 0) ? 0 : part[t - 1];
#pragma unroll
    for (int i = 0; i < 32; i++) {
        g_off[base + i] = run;
        g_cur[base + i] = run;
        run += g_deg[base + i];
    }
    if (t == 511) g_off[NND] = part[511];
}

__global__ void k_fill(const int* __restrict__ src, const int* __restrict__ dst) {
    int e = blockIdx.x * blockDim.x + threadIdx.x;
    if (e < EDG) {
        int d = dst[e];
        int p = atomicAdd(&g_cur[d], 1);
        g_csr[p] = src[e];
    }
}

// =====================================================================
// Input projection + positional encoding: h = x @ Win + bin + pe[s]
// =====================================================================
__global__ void k_input(const float* __restrict__ x, const float* __restrict__ Win,
                        const float* __restrict__ bin, const float* __restrict__ pe) {
    int idx = blockIdx.x * blockDim.x + threadIdx.x;
    if (idx >= NND * DD) return;
    int n = idx >> 7;
    int d = idx & 127;
    int s = (n / NNPG) % SS;
    float acc = bin[d] + pe[s * DD + d];
    const float* xr = x + n * 9;
#pragma unroll
    for (int f = 0; f < 9; f++) acc = fmaf(xr[f], Win[f * DD + d], acc);
    g_h[idx] = acc;
}

// =====================================================================
// Fused QKVS GEMM on tensor cores: mma.sync m16n8k8 tf32.
// A and B both staged in smem in FRAGMENT ORDER with bank swizzles.
// K in 4 quarters of 32. Warp = 32 rows x 64 cols.
// Inner loop per warp-ks: 2 LDS.128 (A) + 4 LDS.128 (B, pair-packed) + 16 MMA.
// =====================================================================
__device__ __forceinline__ uint32_t f2tf32(float f) {
    uint32_t r;
    asm("cvt.rna.tf32.f32 %0, %1;" : "=r"(r) : "f"(f));
    return r;
}

__device__ __forceinline__ void mma_tf32(float* d, const uint32_t* a, const uint32_t* b) {
    asm("mma.sync.aligned.m16n8k8.row.col.f32.tf32.tf32.f32 "
        "{%0,%1,%2,%3}, {%4,%5,%6,%7}, {%8,%9}, {%0,%1,%2,%3};"
        : "+f"(d[0]), "+f"(d[1]), "+f"(d[2]), "+f"(d[3])
        : "r"(a[0]), "r"(a[1]), "r"(a[2]), "r"(a[3]), "r"(b[0]), "r"(b[1]));
}

__global__ __launch_bounds__(256, 2) void k_gemm(
    const float* __restrict__ Wq, const float* __restrict__ Wk,
    const float* __restrict__ Wv, const float* __restrict__ Ws,
    const float* __restrict__ bq, const float* __restrict__ bk,
    const float* __restrict__ bv, const float* __restrict__ bs)
{
    // per k-quarter (4 ks steps):
    // sA[ks][mtile(8)][lane(32)][a0..a3], uint4-index swizzled ^ (ks&3)
    // sB[ks][npair(8)][lane(32)][nt0b0,nt0b1,nt1b0,nt1b1], swizzled ^ npair
    __shared__ uint32_t sA[4 * 8 * 32 * 4];   // 16 KB
    __shared__ uint32_t sB[4 * 8 * 32 * 4];   // 16 KB

    int mat  = blockIdx.y;
    int row0 = blockIdx.x * 128;
    const float* W    = (mat == 0) ? Wq : (mat == 1) ? Wk : (mat == 2) ? Wv : Ws;
    const float* bias = (mat == 0) ? bq : (mat == 1) ? bk : (mat == 2) ? bv : bs;

    int tid  = threadIdx.x;
    int lane = tid & 31;
    int wid  = tid >> 5;
    int rg   = wid >> 1;           // 0..3 : rows rg*32..rg*32+31
    int cg   = wid & 1;            // 0..1 : cols cg*64..cg*64+63
    int gid  = lane >> 2;
    int tig  = lane & 3;

    float acc[2][8][4];
#pragma unroll
    for (int rt = 0; rt < 2; rt++)
#pragma unroll
        for (int nt = 0; nt < 8; nt++)
#pragma unroll
            for (int c = 0; c < 4; c++) acc[rt][nt][c] = 0.f;

    for (int q = 0; q < 4; q++) {          // k-quarter: k0 = q*32
        __syncthreads();
        // ---- stage A (128 rows x 32 k) in fragment order ----
#pragma unroll
        for (int i = 0; i < 4; i++) {
            int e4 = tid + i * 256;        // 0..1023
            int m  = e4 >> 3;              // row 0..127
            int kq = e4 & 7;               // float4 within 32 k
            float4 v = *(const float4*)&g_h[(size_t)(row0 + m) * 128 + q * 32 + kq * 4];
            int ks   = kq >> 1;
            int kin0 = (kq & 1) * 4;
            int r = m & 15, mtile = m >> 4, gd = r & 7;
            int jb = (r >= 8 ? 1 : 0) + (kin0 ? 2 : 0);
            int b4 = (ks * 8 + mtile) * 32 + gd * 4;   // + tig, ^ (ks&3)
            float vv[4] = {v.x, v.y, v.z, v.w};
#pragma unroll
            for (int c = 0; c < 4; c++)
                sA[(((b4 + c) ^ (ks & 3)) << 2) + jb] = f2tf32(vv[c]);
        }
        // ---- stage B (32 k x 128 n) in fragment order, pair-packed ----
#pragma unroll
        for (int i = 0; i < 4; i++) {
            int e4 = tid + i * 256;
            int kk = e4 >> 5;              // 0..31
            int n4 = e4 & 31;
            float4 w = *(const float4*)&W[(size_t)(q * 32 + kk) * 128 + n4 * 4];
            int ks = kk >> 3, kin = kk & 7;
            float wv[4] = {w.x, w.y, w.z, w.w};
#pragma unroll
            for (int c = 0; c < 4; c++) {
                int n = n4 * 4 + c;
                int nt = n >> 3, npair = nt >> 1;
                int l = (n & 7) * 4 + (kin & 3);
                int b4 = ((ks * 8 + npair) * 32 + l) ^ npair;
                sB[(b4 << 2) + (nt & 1) * 2 + (kin >> 2)] = f2tf32(wv[c]);
            }
        }
        __syncthreads();

#pragma unroll
        for (int ks = 0; ks < 4; ks++) {
            uint4 a0 = ((const uint4*)sA)[((ks * 8 + rg * 2 + 0) * 32 + lane) ^ (ks & 3)];
            uint4 a1 = ((const uint4*)sA)[((ks * 8 + rg * 2 + 1) * 32 + lane) ^ (ks & 3)];
#pragma unroll
            for (int p = 0; p < 4; p++) {
                int npair = cg * 4 + p;
                uint4 bf = ((const uint4*)sB)[(((ks * 8 + npair) * 32 + lane) ^ npair)];
                uint32_t b0[2] = {bf.x, bf.y};
                uint32_t b1[2] = {bf.z, bf.w};
                mma_tf32(acc[0][2 * p],     (const uint32_t*)&a0, b0);
                mma_tf32(acc[0][2 * p + 1], (const uint32_t*)&a0, b1);
                mma_tf32(acc[1][2 * p],     (const uint32_t*)&a1, b0);
                mma_tf32(acc[1][2 * p + 1], (const uint32_t*)&a1, b1);
            }
        }
    }

    // epilogue: bias + store
#pragma unroll
    for (int nt = 0; nt < 8; nt++) {
        int c = cg * 64 + nt * 8 + tig * 2;
        float b0 = bias[c], b1 = bias[c + 1];
#pragma unroll
        for (int rt = 0; rt < 2; rt++) {
            int r = row0 + rg * 32 + rt * 16 + gid;
            float* o0 = g_qkvs + (size_t)r * 512 + mat * 128 + c;
            float* o1 = g_qkvs + (size_t)(r + 8) * 512 + mat * 128 + c;
            *(float2*)o0 = make_float2(acc[rt][nt][0] + b0, acc[rt][nt][1] + b1);
            *(float2*)o1 = make_float2(acc[rt][nt][2] + b0, acc[rt][nt][3] + b1);
        }
    }
}

// =====================================================================
// Fused attention: one warp per dst node. (unchanged from round 3)
// =====================================================================
__global__ __launch_bounds__(256) void k_attn(
    const float* __restrict__ Wb, const float* __restrict__ bb,
    const float* __restrict__ lng, const float* __restrict__ lnb)
{
    int gw = (blockIdx.x * 256 + threadIdx.x) >> 5;   // node id
    if (gw >= NND) return;
    int lane = threadIdx.x & 31;
    int t  = lane & 15;          // 16-lane slot within edge
    int eq = lane >> 4;          // edge slot (0/1)

    const float* qrow = g_qkvs + (size_t)gw * 512;
    float4 q1 = ((const float4*)qrow)[t];
    float4 q2 = ((const float4*)qrow)[16 + t];
    q1.x *= .25f; q1.y *= .25f; q1.z *= .25f; q1.w *= .25f;
    q2.x *= .25f; q2.y *= .25f; q2.z *= .25f; q2.w *= .25f;

    float ac1[4] = {0.f, 0.f, 0.f, 0.f};
    float ac2[4] = {0.f, 0.f, 0.f, 0.f};
    float den1 = 0.f, den2 = 0.f;

    int beg = g_off[gw], end = g_off[gw + 1];
    for (int base = beg; base < end; base += 32) {
        int cnt = min(32, end - base);
        int id = (base + lane < end) ? g_csr[base + lane] : 0;
#pragma unroll 2
        for (int e = 0; e < cnt; e += 2) {
            int ee = e + eq;
            bool act = ee < cnt;
            int s = __shfl_sync(0xffffffffu, id, ee & 31);
            const float4* krow = (const float4*)(g_qkvs + (size_t)s * 512 + 128);
            const float4* vrow = (const float4*)(g_qkvs + (size_t)s * 512 + 256);
            float4 k1 = krow[t];
            float4 k2 = krow[16 + t];
            float4 v1 = vrow[t];
            float4 v2 = vrow[16 + t];
            float d1 = q1.x * k1.x + q1.y * k1.y + q1.z * k1.z + q1.w * k1.w;
            float d2 = q2.x * k2.x + q2.y * k2.y + q2.z * k2.z + q2.w * k2.w;
            d1 += __shfl_xor_sync(0xffffffffu, d1, 1);
            d2 += __shfl_xor_sync(0xffffffffu, d2, 1);
            d1 += __shfl_xor_sync(0xffffffffu, d1, 2);
            d2 += __shfl_xor_sync(0xffffffffu, d2, 2);
            float scsel = (lane & 1) ? d2 : d1;
            float p = act ? __expf(scsel) : 0.f;
            float po = __shfl_xor_sync(0xffffffffu, p, 1);
            float p1 = (lane & 1) ? po : p;
            float p2 = (lane & 1) ? p : po;
            ac1[0] += p1 * v1.x; ac1[1] += p1 * v1.y;
            ac1[2] += p1 * v1.z; ac1[3] += p1 * v1.w;
            ac2[0] += p2 * v2.x; ac2[1] += p2 * v2.y;
            ac2[2] += p2 * v2.z; ac2[3] += p2 * v2.w;
            den1 += p1; den2 += p2;
        }
    }

#pragma unroll
    for (int j = 0; j < 4; j++) {
        ac1[j] += __shfl_xor_sync(0xffffffffu, ac1[j], 16);
        ac2[j] += __shfl_xor_sync(0xffffffffu, ac2[j], 16);
    }
    den1 += __shfl_xor_sync(0xffffffffu, den1, 16);
    den2 += __shfl_xor_sync(0xffffffffu, den2, 16);

    float inv1 = 1.f / (den1 + 1e-16f);
    float inv2 = 1.f / (den2 + 1e-16f);
    float ag1[4], ag2[4];
#pragma unroll
    for (int j = 0; j < 4; j++) { ag1[j] = ac1[j] * inv1; ag2[j] = ac2[j] * inv2; }

    int dA = t * 4, dB = 64 + t * 4;
    float4 xa = ((const float4*)(qrow + 384))[t];
    float4 xb = ((const float4*)(qrow + 384))[16 + t];
    float xrA[4] = {xa.x, xa.y, xa.z, xa.w};
    float xrB[4] = {xb.x, xb.y, xb.z, xb.w};

    float part = 0.f;
#pragma unroll
    for (int j = 0; j < 4; j++) {
        part += ag1[j] * Wb[dA + j] + xrA[j] * Wb[128 + dA + j]
              + (ag1[j] - xrA[j]) * Wb[256 + dA + j];
        part += ag2[j] * Wb[dB + j] + xrB[j] * Wb[128 + dB + j]
              + (ag2[j] - xrB[j]) * Wb[256 + dB + j];
    }
#pragma unroll
    for (int o = 16; o; o >>= 1) part += __shfl_xor_sync(0xffffffffu, part, o);
    float beta = 1.f / (1.f + __expf(-(0.5f * part + bb[0])));

    float4 ha = ((const float4*)(g_h + (size_t)gw * 128))[t];
    float4 hb = ((const float4*)(g_h + (size_t)gw * 128))[16 + t];
    float hvA[4] = {ha.x, ha.y, ha.z, ha.w};
    float hvB[4] = {hb.x, hb.y, hb.z, hb.w};
    float yA[4], yB[4];
#pragma unroll
    for (int j = 0; j < 4; j++) {
        yA[j] = hvA[j] + beta * xrA[j] + (1.f - beta) * ag1[j];
        yB[j] = hvB[j] + beta * xrB[j] + (1.f - beta) * ag2[j];
    }

    float ssum = yA[0] + yA[1] + yA[2] + yA[3] + yB[0] + yB[1] + yB[2] + yB[3];
#pragma unroll
    for (int o = 16; o; o >>= 1) ssum += __shfl_xor_sync(0xffffffffu, ssum, o);
    float mean = ssum * (1.f / 256.f);

    float vs = 0.f;
#pragma unroll
    for (int j = 0; j < 4; j++) {
        float ta = yA[j] - mean; vs += ta * ta;
        float tb = yB[j] - mean; vs += tb * tb;
    }
#pragma unroll
    for (int o = 16; o; o >>= 1) vs += __shfl_xor_sync(0xffffffffu, vs, o);
    float rstd = rsqrtf(vs * (1.f / 256.f) + 1e-5f);

    if (eq == 0) {
        float4 oA, oB;
        oA.x = (yA[0] - mean) * rstd * lng[dA + 0] + lnb[dA + 0];
        oA.y = (yA[1] - mean) * rstd * lng[dA + 1] + lnb[dA + 1];
        oA.z = (yA[2] - mean) * rstd * lng[dA + 2] + lnb[dA + 2];
        oA.w = (yA[3] - mean) * rstd * lng[dA + 3] + lnb[dA + 3];
        oB.x = (yB[0] - mean) * rstd * lng[dB + 0] + lnb[dB + 0];
        oB.y = (yB[1] - mean) * rstd * lng[dB + 1] + lnb[dB + 1];
        oB.z = (yB[2] - mean) * rstd * lng[dB + 2] + lnb[dB + 2];
        oB.w = (yB[3] - mean) * rstd * lng[dB + 3] + lnb[dB + 3];
        ((float4*)(g_h + (size_t)gw * 128))[t] = oA;
        ((float4*)(g_h + (size_t)gw * 128))[16 + t] = oB;
    }
}

// =====================================================================
// Output head: out = relu(h @ Wo1 + bo1) @ Wo2 + bo2    (16 nodes / block)
// =====================================================================
__global__ __launch_bounds__(256) void k_out(
    const float* __restrict__ Wo1, const float* __restrict__ bo1,
    const float* __restrict__ Wo2, const float* __restrict__ bo2,
    float* __restrict__ out)
{
    __shared__ float w1[128 * 64];
    __shared__ float hs[16][128];
    __shared__ float ts[16][64];
    int tid = threadIdx.x;
    int n0 = blockIdx.x * 16;

    for (int i = tid; i < 128 * 64 / 4; i += 256)
        ((float4*)w1)[i] = ((const float4*)Wo1)[i];
    for (int i = tid; i < 16 * 128 / 4; i += 256)
        ((float4*)&hs[0][0])[i] = ((const float4*)(g_h + (size_t)n0 * 128))[i];
    __syncthreads();

    int j = tid & 63, g0 = tid >> 6;
    float a0 = bo1[j], a1 = a0, a2 = a0, a3 = a0;
#pragma unroll 8
    for (int d = 0; d < 128; d++) {
        float w = w1[d * 64 + j];
        a0 = fmaf(hs[g0 +  0][d], w, a0);
        a1 = fmaf(hs[g0 +  4][d], w, a1);
        a2 = fmaf(hs[g0 +  8][d], w, a2);
        a3 = fmaf(hs[g0 + 12][d], w, a3);
    }
    ts[g0 +  0][j] = fmaxf(a0, 0.f);
    ts[g0 +  4][j] = fmaxf(a1, 0.f);
    ts[g0 +  8][j] = fmaxf(a2, 0.f);
    ts[g0 + 12][j] = fmaxf(a3, 0.f);
    __syncthreads();

    if (tid < 48) {
        int n = tid / 3, c = tid % 3;
        float o = bo2[c];
#pragma unroll
        for (int k = 0; k < 64; k++) o = fmaf(ts[n][k], Wo2[k * 3 + c], o);
        out[(size_t)(n0 + n) * 3 + c] = o;
    }
}

// =====================================================================
// launcher  (k_gemm layer0 kept in the ncu-captured slot)
// =====================================================================
extern "C" void kernel_launch(void* const* d_in, const int* in_sizes, int n_in,
                              void* d_out, int out_size)
{
    const float* x    = (const float*)d_in[0];
    const int*   ei   = (const int*)  d_in[1];
    const float* pe   = (const float*)d_in[2];
    const float* Win  = (const float*)d_in[3];
    const float* bin  = (const float*)d_in[4];
    const float* Wq   = (const float*)d_in[5];
    const float* bq   = (const float*)d_in[6];
    const float* Wk   = (const float*)d_in[7];
    const float* bk   = (const float*)d_in[8];
    const float* Wv   = (const float*)d_in[9];
    const float* bv   = (const float*)d_in[10];
    const float* Ws   = (const float*)d_in[11];
    const float* bs   = (const float*)d_in[12];
    const float* Wb   = (const float*)d_in[13];
    const float* bb   = (const float*)d_in[14];
    const float* lng  = (const float*)d_in[15];
    const float* lnb  = (const float*)d_in[16];
    const float* Wo1  = (const float*)d_in[17];
    const float* bo1  = (const float*)d_in[18];
    const float* Wo2  = (const float*)d_in[19];
    const float* bo2  = (const float*)d_in[20];
    float* out = (float*)d_out;

    const int* src = ei;
    const int* dst = ei + EDG;

    k_zero_deg<<<NND / 256, 256>>>();
    k_count<<<EDG / 256, 256>>>(dst);
    k_input<<<NND * DD / 256, 256>>>(x, Win, bin, pe);

    dim3 gg(NND / 128, 4);
    k_gemm<<<gg, 256>>>(Wq, Wk, Wv, Ws, bq, bk, bv, bs);

    k_scan<<<1, 512>>>();
    k_fill<<<EDG / 256, 256>>>(src, dst);

    k_attn<<<NND / 8, 256>>>(Wb, bb, lng, lnb);
    for (int l = 1; l < LL; l++) {
        k_gemm<<<gg, 256>>>(Wq + (size_t)l * DD * DD, Wk + (size_t)l * DD * DD,
                            Wv + (size_t)l * DD * DD, Ws + (size_t)l * DD * DD,
                            bq + l * DD, bk + l * DD, bv + l * DD, bs + l * DD);
        k_attn<<<NND / 8, 256>>>(Wb + l * 384, bb + l, lng + l * DD, lnb + l * DD);
    }

    k_out<<<NND / 16, 256>>>(Wo1, bo1, Wo2, bo2, out);
}

// round 5
// speedup vs baseline: 1.7364x; 1.0973x over previous
#include <cuda_runtime.h>
#include <cuda_bf16.h>
#include <cstdint>

// ---- problem constants (fixed by the dataset) ----
#define NND   16384      // nodes = B*S*NN
#define EDG   262144     // edges
#define DD    128        // hidden dim
#define SS    128        // seq len
#define NNPG  64         // nodes per graph-step
#define LL    6          // layers

// ---- scratch (device globals; no allocation allowed) ----
__device__ float g_h[NND * DD];                        // 8 MB hidden state
__device__ float g_qkvs[(size_t)NND * 2 * DD];         // 16 MB q|xr per node (fp32)
__device__ __nv_bfloat16 g_kv[(size_t)NND * 2 * DD];   // 8 MB k|v per node (bf16)
__device__ int   g_deg[NND];
__device__ int   g_off[NND + 1];
__device__ int   g_cur[NND];
__device__ int   g_csr[EDG];                           // src id per CSR slot

// =====================================================================
// CSR build
// =====================================================================
__global__ void k_zero_deg() {
    int i = blockIdx.x * blockDim.x + threadIdx.x;
    if (i < NND) g_deg[i] = 0;
}

__global__ void k_count(const int* __restrict__ dst) {
    int e = blockIdx.x * blockDim.x + threadIdx.x;
    if (e < EDG) atomicAdd(&g_deg[dst[e]], 1);
}

__global__ void k_scan() {
    __shared__ int part[512];
    int t = threadIdx.x;
    int base = t * 32;
    int s = 0;
#pragma unroll
    for (int i = 0; i < 32; i++) s += g_deg[base + i];
    part[t] = s;
    __syncthreads();
    for (int ofs = 1; ofs < 512; ofs <<= 1) {
        int v = (t >= ofs) ? part[t - ofs] : 0;
        __syncthreads();
        part[t] += v;
        __syncthreads();
    }
    int run = (t == 0) ? 0 : part[t - 1];
#pragma unroll
    for (int i = 0; i < 32; i++) {
        g_off[base + i] = run;
        g_cur[base + i] = run;
        run += g_deg[base + i];
    }
    if (t == 511) g_off[NND] = part[511];
}

__global__ void k_fill(const int* __restrict__ src, const int* __restrict__ dst) {
    int e = blockIdx.x * blockDim.x + threadIdx.x;
    if (e < EDG) {
        int d = dst[e];
        int p = atomicAdd(&g_cur[d], 1);
        g_csr[p] = src[e];
    }
}

// =====================================================================
// Input projection + positional encoding: h = x @ Win + bin + pe[s]
// =====================================================================
__global__ void k_input(const float* __restrict__ x, const float* __restrict__ Win,
                        const float* __restrict__ bin, const float* __restrict__ pe) {
    int idx = blockIdx.x * blockDim.x + threadIdx.x;
    if (idx >= NND * DD) return;
    int n = idx >> 7;
    int d = idx & 127;
    int s = (n / NNPG) % SS;
    float acc = bin[d] + pe[s * DD + d];
    const float* xr = x + n * 9;
#pragma unroll
    for (int f = 0; f < 9; f++) acc = fmaf(xr[f], Win[f * DD + d], acc);
    g_h[idx] = acc;
}

// =====================================================================
// Fused QKVS GEMM, tf32 mma.sync, software-pipelined:
//  - B (weights) staged ONCE in fragment order (64 KB smem)
//  - A double-buffered per k-quarter, prefetch q+1 into regs during compute q
//  - one __syncthreads per quarter
//  - k (mat1) / v (mat2) written as bf16 into g_kv; q/xr fp32 into g_qkvs
// =====================================================================
__device__ __forceinline__ uint32_t f2tf32(float f) {
    uint32_t r;
    asm("cvt.rna.tf32.f32 %0, %1;" : "=r"(r) : "f"(f));
    return r;
}

__device__ __forceinline__ void mma_tf32(float* d, const uint32_t* a, const uint32_t* b) {
    asm("mma.sync.aligned.m16n8k8.row.col.f32.tf32.tf32.f32 "
        "{%0,%1,%2,%3}, {%4,%5,%6,%7}, {%8,%9}, {%0,%1,%2,%3};"
        : "+f"(d[0]), "+f"(d[1]), "+f"(d[2]), "+f"(d[3])
        : "r"(a[0]), "r"(a[1]), "r"(a[2]), "r"(a[3]), "r"(b[0]), "r"(b[1]));
}

__global__ __launch_bounds__(256, 2) void k_gemm(
    const float* __restrict__ Wq, const float* __restrict__ Wk,
    const float* __restrict__ Wv, const float* __restrict__ Ws,
    const float* __restrict__ bq, const float* __restrict__ bk,
    const float* __restrict__ bv, const float* __restrict__ bs)
{
    // dynamic smem: sB[16ks][8npair][32lane][4u32] = 64 KB, then sA 2 x 16 KB
    extern __shared__ uint32_t smem[];
    uint32_t* sB = smem;                 // 16384 u32
    uint32_t* sA = smem + 16384;         // 2 * 4096 u32

    int mat  = blockIdx.y;
    int row0 = blockIdx.x * 128;
    const float* W    = (mat == 0) ? Wq : (mat == 1) ? Wk : (mat == 2) ? Wv : Ws;
    const float* bias = (mat == 0) ? bq : (mat == 1) ? bk : (mat == 2) ? bv : bs;

    int tid  = threadIdx.x;
    int lane = tid & 31;
    int wid  = tid >> 5;
    int rg   = wid >> 1;           // rows rg*32..+31
    int cg   = wid & 1;            // cols cg*64..+63
    int gid  = lane >> 2;
    int tig  = lane & 3;

    float acc[2][8][4];
#pragma unroll
    for (int rt = 0; rt < 2; rt++)
#pragma unroll
        for (int nt = 0; nt < 8; nt++)
#pragma unroll
            for (int c = 0; c < 4; c++) acc[rt][nt][c] = 0.f;

    // ---- stage ALL of B (128k x 128n) in fragment order, pair-packed ----
#pragma unroll
    for (int i = 0; i < 16; i++) {
        int e4 = tid + i * 256;            // 0..4095
        int kk = e4 >> 5;                  // 0..127
        int n4 = e4 & 31;
        float4 w = *(const float4*)&W[(size_t)kk * 128 + n4 * 4];
        int ks = kk >> 3, kin = kk & 7;
        float wv[4] = {w.x, w.y, w.z, w.w};
#pragma unroll
        for (int c = 0; c < 4; c++) {
            int n = n4 * 4 + c;
            int nt = n >> 3, npair = nt >> 1;
            int l = (n & 7) * 4 + (kin & 3);
            int b4 = ((ks * 8 + npair) * 32 + l) ^ npair;
            sB[(b4 << 2) + (nt & 1) * 2 + (kin >> 2)] = f2tf32(wv[c]);
        }
    }

    // ---- prefetch A quarter 0 ----
    float4 vA[4];
#pragma unroll
    for (int i = 0; i < 4; i++) {
        int e4 = tid + i * 256;
        int m  = e4 >> 3, kq = e4 & 7;
        vA[i] = *(const float4*)&g_h[(size_t)(row0 + m) * 128 + kq * 4];
    }

#pragma unroll
    for (int q = 0; q < 4; q++) {
        uint32_t* A = sA + (q & 1) * 4096;
        // store A quarter q in fragment order
#pragma unroll
        for (int i = 0; i < 4; i++) {
            int e4 = tid + i * 256;
            int m  = e4 >> 3, kq = e4 & 7;
            int ksl  = kq >> 1;
            int kin0 = (kq & 1) * 4;
            int r = m & 15, mtile = m >> 4, gd = r & 7;
            int jb = (r >= 8 ? 1 : 0) + (kin0 ? 2 : 0);
            int b4 = (ksl * 8 + mtile) * 32 + gd * 4;
            float vv[4] = {vA[i].x, vA[i].y, vA[i].z, vA[i].w};
#pragma unroll
            for (int c = 0; c < 4; c++)
                A[(((b4 + c) ^ (ksl & 3)) << 2) + jb] = f2tf32(vv[c]);
        }
        __syncthreads();   // (first iteration also covers sB stores)

        // prefetch next quarter while computing this one
        if (q < 3) {
#pragma unroll
            for (int i = 0; i < 4; i++) {
                int e4 = tid + i * 256;
                int m  = e4 >> 3, kq = e4 & 7;
                vA[i] = *(const float4*)&g_h[(size_t)(row0 + m) * 128 + (q + 1) * 32 + kq * 4];
            }
        }

#pragma unroll
        for (int ksl = 0; ksl < 4; ksl++) {
            int ks = q * 4 + ksl;
            uint4 a0 = ((const uint4*)A)[((ksl * 8 + rg * 2 + 0) * 32 + lane) ^ (ksl & 3)];
            uint4 a1 = ((const uint4*)A)[((ksl * 8 + rg * 2 + 1) * 32 + lane) ^ (ksl & 3)];
#pragma unroll
            for (int p = 0; p < 4; p++) {
                int npair = cg * 4 + p;
                uint4 bf = ((const uint4*)sB)[(((ks * 8 + npair) * 32 + lane) ^ npair)];
                uint32_t b0[2] = {bf.x, bf.y};
                uint32_t b1[2] = {bf.z, bf.w};
                mma_tf32(acc[0][2 * p],     (const uint32_t*)&a0, b0);
                mma_tf32(acc[0][2 * p + 1], (const uint32_t*)&a0, b1);
                mma_tf32(acc[1][2 * p],     (const uint32_t*)&a1, b0);
                mma_tf32(acc[1][2 * p + 1], (const uint32_t*)&a1, b1);
            }
        }
        __syncthreads();   // all reads of this buffer done before it is re-stored
    }

    // ---- epilogue: bias + store (q/xr fp32, k/v bf16) ----
    bool isf32 = (mat == 0 || mat == 3);
    int off = (mat == 0 || mat == 1) ? 0 : 128;
#pragma unroll
    for (int nt = 0; nt < 8; nt++) {
        int c = cg * 64 + nt * 8 + tig * 2;
        float b0 = bias[c], b1 = bias[c + 1];
#pragma unroll
        for (int rt = 0; rt < 2; rt++) {
            int r = row0 + rg * 32 + rt * 16 + gid;
            float v00 = acc[rt][nt][0] + b0, v01 = acc[rt][nt][1] + b1;
            float v10 = acc[rt][nt][2] + b0, v11 = acc[rt][nt][3] + b1;
            if (isf32) {
                *(float2*)(g_qkvs + (size_t)r * 256 + off + c)       = make_float2(v00, v01);
                *(float2*)(g_qkvs + (size_t)(r + 8) * 256 + off + c) = make_float2(v10, v11);
            } else {
                *(__nv_bfloat162*)(g_kv + (size_t)r * 256 + off + c)       = __floats2bfloat162_rn(v00, v01);
                *(__nv_bfloat162*)(g_kv + (size_t)(r + 8) * 256 + off + c) = __floats2bfloat162_rn(v10, v11);
            }
        }
    }
}

// =====================================================================
// Fused attention: one warp per dst node, bf16 k/v.
// lane = eq*16 + t (2 edges in flight). Lane t owns dims [t*8, t*8+8):
// reads ONE uint4 of k and ONE of v per edge (line-minimal: 4 lines/edge).
// Head h = t>>1; dot = 8-dim partial + shfl_xor(1).
// =====================================================================
__global__ __launch_bounds__(256) void k_attn(
    const float* __restrict__ Wb, const float* __restrict__ bb,
    const float* __restrict__ lng, const float* __restrict__ lnb)
{
    int gw = (blockIdx.x * 256 + threadIdx.x) >> 5;   // node id
    if (gw >= NND) return;
    int lane = threadIdx.x & 31;
    int t  = lane & 15;
    int eq = lane >> 4;
    int d0 = t * 8;

    const float* qrow = g_qkvs + (size_t)gw * 256;
    float q[8];
    {
        float4 qa = ((const float4*)qrow)[t * 2];
        float4 qb = ((const float4*)qrow)[t * 2 + 1];
        q[0] = qa.x * .25f; q[1] = qa.y * .25f; q[2] = qa.z * .25f; q[3] = qa.w * .25f;
        q[4] = qb.x * .25f; q[5] = qb.y * .25f; q[6] = qb.z * .25f; q[7] = qb.w * .25f;
    }

    float acc[8] = {0.f, 0.f, 0.f, 0.f, 0.f, 0.f, 0.f, 0.f};
    float den = 0.f;

    int beg = g_off[gw], end = g_off[gw + 1];
    for (int base = beg; base < end; base += 32) {
        int cnt = min(32, end - base);
        int id = (base + lane < end) ? g_csr[base + lane] : 0;
#pragma unroll 2
        for (int e = 0; e < cnt; e += 2) {
            int ee = e + eq;
            bool act = ee < cnt;
            int s = __shfl_sync(0xffffffffu, id, ee & 31);
            const uint4* kvrow = (const uint4*)(g_kv + (size_t)s * 256);
            uint4 kr = kvrow[t];
            uint4 vr = kvrow[16 + t];
            float2 k0 = __bfloat1622float2(*(const __nv_bfloat162*)&kr.x);
            float2 k1 = __bfloat1622float2(*(const __nv_bfloat162*)&kr.y);
            float2 k2 = __bfloat1622float2(*(const __nv_bfloat162*)&kr.z);
            float2 k3 = __bfloat1622float2(*(const __nv_bfloat162*)&kr.w);
            float d = q[0] * k0.x + q[1] * k0.y + q[2] * k1.x + q[3] * k1.y
                    + q[4] * k2.x + q[5] * k2.y + q[6] * k3.x + q[7] * k3.y;
            d += __shfl_xor_sync(0xffffffffu, d, 1);   // full head score
            float p = act ? __expf(d) : 0.f;
            float2 v0 = __bfloat1622float2(*(const __nv_bfloat162*)&vr.x);
            float2 v1 = __bfloat1622float2(*(const __nv_bfloat162*)&vr.y);
            float2 v2 = __bfloat1622float2(*(const __nv_bfloat162*)&vr.z);
            float2 v3 = __bfloat1622float2(*(const __nv_bfloat162*)&vr.w);
            acc[0] += p * v0.x; acc[1] += p * v0.y;
            acc[2] += p * v1.x; acc[3] += p * v1.y;
            acc[4] += p * v2.x; acc[5] += p * v2.y;
            acc[6] += p * v3.x; acc[7] += p * v3.y;
            den += p;
        }
    }

    // reduce across the two edge slots (xor bit 4)
#pragma unroll
    for (int j = 0; j < 8; j++)
        acc[j] += __shfl_xor_sync(0xffffffffu, acc[j], 16);
    den += __shfl_xor_sync(0xffffffffu, den, 16);

    float inv = 1.f / (den + 1e-16f);
    float ag[8];
#pragma unroll
    for (int j = 0; j < 8; j++) ag[j] = acc[j] * inv;

    // xr (skip branch)
    float xr[8];
    {
        float4 xa = ((const float4*)(qrow + 128))[t * 2];
        float4 xb = ((const float4*)(qrow + 128))[t * 2 + 1];
        xr[0] = xa.x; xr[1] = xa.y; xr[2] = xa.z; xr[3] = xa.w;
        xr[4] = xb.x; xr[5] = xb.y; xr[6] = xb.z; xr[7] = xb.w;
    }

    // beta gate (warp sum counts everything twice -> 0.5 factor)
    float part = 0.f;
#pragma unroll
    for (int j = 0; j < 8; j++) {
        int d = d0 + j;
        part += ag[j] * Wb[d] + xr[j] * Wb[128 + d] + (ag[j] - xr[j]) * Wb[256 + d];
    }
#pragma unroll
    for (int o = 16; o; o >>= 1) part += __shfl_xor_sync(0xffffffffu, part, o);
    float beta = 1.f / (1.f + __expf(-(0.5f * part + bb[0])));

    // hn = beta*xr + (1-beta)*agg ; h = LN(h + hn)
    float hv[8];
    {
        float4 ha = ((const float4*)(g_h + (size_t)gw * 128))[t * 2];
        float4 hb = ((const float4*)(g_h + (size_t)gw * 128))[t * 2 + 1];
        hv[0] = ha.x; hv[1] = ha.y; hv[2] = ha.z; hv[3] = ha.w;
        hv[4] = hb.x; hv[5] = hb.y; hv[6] = hb.z; hv[7] = hb.w;
    }
    float y[8];
#pragma unroll
    for (int j = 0; j < 8; j++)
        y[j] = hv[j] + beta * xr[j] + (1.f - beta) * ag[j];

    float ssum = 0.f;
#pragma unroll
    for (int j = 0; j < 8; j++) ssum += y[j];
#pragma unroll
    for (int o = 16; o; o >>= 1) ssum += __shfl_xor_sync(0xffffffffu, ssum, o);
    float mean = ssum * (1.f / 256.f);   // duplicated across eq -> /256

    float vs = 0.f;
#pragma unroll
    for (int j = 0; j < 8; j++) { float tv = y[j] - mean; vs += tv * tv; }
#pragma unroll
    for (int o = 16; o; o >>= 1) vs += __shfl_xor_sync(0xffffffffu, vs, o);
    float rstd = rsqrtf(vs * (1.f / 256.f) + 1e-5f);

    if (eq == 0) {
        float4 oA, oB;
        oA.x = (y[0] - mean) * rstd * lng[d0 + 0] + lnb[d0 + 0];
        oA.y = (y[1] - mean) * rstd * lng[d0 + 1] + lnb[d0 + 1];
        oA.z = (y[2] - mean) * rstd * lng[d0 + 2] + lnb[d0 + 2];
        oA.w = (y[3] - mean) * rstd * lng[d0 + 3] + lnb[d0 + 3];
        oB.x = (y[4] - mean) * rstd * lng[d0 + 4] + lnb[d0 + 4];
        oB.y = (y[5] - mean) * rstd * lng[d0 + 5] + lnb[d0 + 5];
        oB.z = (y[6] - mean) * rstd * lng[d0 + 6] + lnb[d0 + 6];
        oB.w = (y[7] - mean) * rstd * lng[d0 + 7] + lnb[d0 + 7];
        ((float4*)(g_h + (size_t)gw * 128))[t * 2]     = oA;
        ((float4*)(g_h + (size_t)gw * 128))[t * 2 + 1] = oB;
    }
}

// =====================================================================
// Output head: out = relu(h @ Wo1 + bo1) @ Wo2 + bo2    (16 nodes / block)
// =====================================================================
__global__ __launch_bounds__(256) void k_out(
    const float* __restrict__ Wo1, const float* __restrict__ bo1,
    const float* __restrict__ Wo2, const float* __restrict__ bo2,
    float* __restrict__ out)
{
    __shared__ float w1[128 * 64];
    __shared__ float hs[16][128];
    __shared__ float ts[16][64];
    int tid = threadIdx.x;
    int n0 = blockIdx.x * 16;

    for (int i = tid; i < 128 * 64 / 4; i += 256)
        ((float4*)w1)[i] = ((const float4*)Wo1)[i];
    for (int i = tid; i < 16 * 128 / 4; i += 256)
        ((float4*)&hs[0][0])[i] = ((const float4*)(g_h + (size_t)n0 * 128))[i];
    __syncthreads();

    int j = tid & 63, g0 = tid >> 6;
    float a0 = bo1[j], a1 = a0, a2 = a0, a3 = a0;
#pragma unroll 8
    for (int d = 0; d < 128; d++) {
        float w = w1[d * 64 + j];
        a0 = fmaf(hs[g0 +  0][d], w, a0);
        a1 = fmaf(hs[g0 +  4][d], w, a1);
        a2 = fmaf(hs[g0 +  8][d], w, a2);
        a3 = fmaf(hs[g0 + 12][d], w, a3);
    }
    ts[g0 +  0][j] = fmaxf(a0, 0.f);
    ts[g0 +  4][j] = fmaxf(a1, 0.f);
    ts[g0 +  8][j] = fmaxf(a2, 0.f);
    ts[g0 + 12][j] = fmaxf(a3, 0.f);
    __syncthreads();

    if (tid < 48) {
        int n = tid / 3, c = tid % 3;
        float o = bo2[c];
#pragma unroll
        for (int k = 0; k < 64; k++) o = fmaf(ts[n][k], Wo2[k * 3 + c], o);
        out[(size_t)(n0 + n) * 3 + c] = o;
    }
}

// =====================================================================
// launcher  (k_gemm layer0 kept in the ncu-captured slot)
// =====================================================================
#define GEMM_SMEM (96 * 1024)

extern "C" void kernel_launch(void* const* d_in, const int* in_sizes, int n_in,
                              void* d_out, int out_size)
{
    const float* x    = (const float*)d_in[0];
    const int*   ei   = (const int*)  d_in[1];
    const float* pe   = (const float*)d_in[2];
    const float* Win  = (const float*)d_in[3];
    const float* bin  = (const float*)d_in[4];
    const float* Wq   = (const float*)d_in[5];
    const float* bq   = (const float*)d_in[6];
    const float* Wk   = (const float*)d_in[7];
    const float* bk   = (const float*)d_in[8];
    const float* Wv   = (const float*)d_in[9];
    const float* bv   = (const float*)d_in[10];
    const float* Ws   = (const float*)d_in[11];
    const float* bs   = (const float*)d_in[12];
    const float* Wb   = (const float*)d_in[13];
    const float* bb   = (const float*)d_in[14];
    const float* lng  = (const float*)d_in[15];
    const float* lnb  = (const float*)d_in[16];
    const float* Wo1  = (const float*)d_in[17];
    const float* bo1  = (const float*)d_in[18];
    const float* Wo2  = (const float*)d_in[19];
    const float* bo2  = (const float*)d_in[20];
    float* out = (float*)d_out;

    const int* src = ei;
    const int* dst = ei + EDG;

    static bool attr_set = false;
    if (!attr_set) {
        cudaFuncSetAttribute(k_gemm, cudaFuncAttributeMaxDynamicSharedMemorySize, GEMM_SMEM);
        attr_set = true;
    }

    k_zero_deg<<<NND / 256, 256>>>();
    k_count<<<EDG / 256, 256>>>(dst);
    k_input<<<NND * DD / 256, 256>>>(x, Win, bin, pe);

    dim3 gg(NND / 128, 4);
    k_gemm<<<gg, 256, GEMM_SMEM>>>(Wq, Wk, Wv, Ws, bq, bk, bv, bs);

    k_scan<<<1, 512>>>();
    k_fill<<<EDG / 256, 256>>>(src, dst);

    k_attn<<<NND / 8, 256>>>(Wb, bb, lng, lnb);
    for (int l = 1; l < LL; l++) {
        k_gemm<<<gg, 256, GEMM_SMEM>>>(Wq + (size_t)l * DD * DD, Wk + (size_t)l * DD * DD,
                                       Wv + (size_t)l * DD * DD, Ws + (size_t)l * DD * DD,
                                       bq + l * DD, bk + l * DD, bv + l * DD, bs + l * DD);
        k_attn<<<NND / 8, 256>>>(Wb + l * 384, bb + l, lng + l * DD, lnb + l * DD);
    }

    k_out<<<NND / 16, 256>>>(Wo1, bo1, Wo2, bo2, out);
}

// round 6
// speedup vs baseline: 1.7899x; 1.0308x over previous
#include <cuda_runtime.h>
#include <cuda_bf16.h>
#include <cstdint>

// ---- problem constants (fixed by the dataset) ----
#define NND   16384      // nodes = B*S*NN
#define EDG   262144     // edges
#define DD    128        // hidden dim
#define SS    128        // seq len
#define NNPG  64         // nodes per graph-step
#define LL    6          // layers

// ---- scratch (device globals; no allocation allowed) ----
__device__ float g_h[NND * DD];                        // 8 MB hidden state
__device__ float g_qkvs[(size_t)NND * 2 * DD];         // 16 MB q|xr per node (fp32)
__device__ __nv_bfloat16 g_kv[(size_t)NND * 2 * DD];   // 8 MB k|v per node (bf16)
__device__ uint32_t g_Wfrag[24 * 16384];               // 1.5 MB fragment-order tf32 weights
__device__ int   g_deg[NND];
__device__ int   g_off[NND + 1];
__device__ int   g_cur[NND];
__device__ int   g_csr[EDG];                           // src id per CSR slot

// =====================================================================
// helpers
// =====================================================================
__device__ __forceinline__ uint32_t f2tf32(float f) {
    uint32_t r;
    asm("cvt.rna.tf32.f32 %0, %1;" : "=r"(r) : "f"(f));
    return r;
}

__device__ __forceinline__ void mma_tf32(float* d, const uint32_t* a, const uint32_t* b) {
    asm("mma.sync.aligned.m16n8k8.row.col.f32.tf32.tf32.f32 "
        "{%0,%1,%2,%3}, {%4,%5,%6,%7}, {%8,%9}, {%0,%1,%2,%3};"
        : "+f"(d[0]), "+f"(d[1]), "+f"(d[2]), "+f"(d[3])
        : "r"(a[0]), "r"(a[1]), "r"(a[2]), "r"(a[3]), "r"(b[0]), "r"(b[1]));
}

// =====================================================================
// k_prep: convert all 24 weight mats to fragment-order tf32 in global,
// and zero g_deg (blocks 24..27).
// Fragment layout per mat (16384 u32): u4index = (ks*8 + npair)*32 + l,
// word = (nt&1)*2 + (kin>>2).  (no xor swizzle: gmem has no banks)
// =====================================================================
__global__ void k_prep(const float* __restrict__ Wq, const float* __restrict__ Wk,
                       const float* __restrict__ Wv, const float* __restrict__ Ws) {
    int b = blockIdx.x;
    int tid = threadIdx.x;
    if (b >= 24) {
        for (int i = (b - 24) * 4096 + tid; i < (b - 23) * 4096; i += 256)
            g_deg[i] = 0;
        return;
    }
    int l = b >> 2, mat = b & 3;
    const float* W = ((mat == 0) ? Wq : (mat == 1) ? Wk : (mat == 2) ? Wv : Ws)
                   + (size_t)l * 16384;
    uint32_t* out = g_Wfrag + (size_t)b * 16384;
#pragma unroll
    for (int i = 0; i < 16; i++) {
        int e4 = tid + i * 256;            // 0..4095
        int kk = e4 >> 5;                  // 0..127
        int n4 = e4 & 31;
        float4 w = *(const float4*)&W[(size_t)kk * 128 + n4 * 4];
        int ks = kk >> 3, kin = kk & 7;
        float wv[4] = {w.x, w.y, w.z, w.w};
#pragma unroll
        for (int c = 0; c < 4; c++) {
            int n = n4 * 4 + c;
            int nt = n >> 3, npair = nt >> 1;
            int ll = (n & 7) * 4 + (kin & 3);
            int u4 = (ks * 8 + npair) * 32 + ll;
            out[(u4 << 2) + (nt & 1) * 2 + (kin >> 2)] = f2tf32(wv[c]);
        }
    }
}

// =====================================================================
// CSR build
// =====================================================================
__global__ void k_count(const int* __restrict__ dst) {
    int e = blockIdx.x * blockDim.x + threadIdx.x;
    if (e < EDG) atomicAdd(&g_deg[dst[e]], 1);
}

__global__ void k_scan() {
    __shared__ int part[512];
    int t = threadIdx.x;
    int base = t * 32;
    int s = 0;
#pragma unroll
    for (int i = 0; i < 32; i++) s += g_deg[base + i];
    part[t] = s;
    __syncthreads();
    for (int ofs = 1; ofs < 512; ofs <<= 1) {
        int v = (t >= ofs) ? part[t - ofs] : 0;
        __syncthreads();
        part[t] += v;
        __syncthreads();
    }
    int run = (t == 0) ? 0 : part[t - 1];
#pragma unroll
    for (int i = 0; i < 32; i++) {
        g_off[base + i] = run;
        g_cur[base + i] = run;
        run += g_deg[base + i];
    }
    if (t == 511) g_off[NND] = part[511];
}

__global__ void k_fill(const int* __restrict__ src, const int* __restrict__ dst) {
    int e = blockIdx.x * blockDim.x + threadIdx.x;
    if (e < EDG) {
        int d = dst[e];
        int p = atomicAdd(&g_cur[d], 1);
        g_csr[p] = src[e];
    }
}

// =====================================================================
// Input projection + positional encoding: h = x @ Win + bin + pe[s]
// =====================================================================
__global__ void k_input(const float* __restrict__ x, const float* __restrict__ Win,
                        const float* __restrict__ bin, const float* __restrict__ pe) {
    int idx = blockIdx.x * blockDim.x + threadIdx.x;
    if (idx >= NND * DD) return;
    int n = idx >> 7;
    int d = idx & 127;
    int s = (n / NNPG) % SS;
    float acc = bin[d] + pe[s * DD + d];
    const float* xr = x + n * 9;
#pragma unroll
    for (int f = 0; f < 9; f++) acc = fmaf(xr[f], Win[f * DD + d], acc);
    g_h[idx] = acc;
}

// =====================================================================
// Fused QKVS GEMM, tf32 mma.sync:
//  - B fragments read straight from preconverted g_Wfrag (coalesced
//    LDG.128, L2-resident, +1-ks software prefetch) — no B smem at all
//  - A double-buffered in smem (fragment order, raw fp32 bits: HMMA
//    truncates to tf32), prefetch next quarter during compute
//  - k/v written bf16 to g_kv, q/xr fp32 to g_qkvs
// =====================================================================
__global__ __launch_bounds__(256, 2) void k_gemm(
    int layer,
    const float* __restrict__ bq, const float* __restrict__ bk,
    const float* __restrict__ bv, const float* __restrict__ bs)
{
    __shared__ uint32_t sA[2 * 4096];   // 32 KB, double-buffered A

    int mat  = blockIdx.y;
    int row0 = blockIdx.x * 128;
    const float* bias = (mat == 0) ? bq : (mat == 1) ? bk : (mat == 2) ? bv : bs;
    const uint4* Bf = (const uint4*)(g_Wfrag + (size_t)(layer * 4 + mat) * 16384);

    int tid  = threadIdx.x;
    int lane = tid & 31;
    int wid  = tid >> 5;
    int rg   = wid >> 1;           // rows rg*32..+31
    int cg   = wid & 1;            // cols cg*64..+63
    int gid  = lane >> 2;
    int tig  = lane & 3;

    float acc[2][8][4];
#pragma unroll
    for (int rt = 0; rt < 2; rt++)
#pragma unroll
        for (int nt = 0; nt < 8; nt++)
#pragma unroll
            for (int c = 0; c < 4; c++) acc[rt][nt][c] = 0.f;

    // ---- prefetch A quarter 0 ----
    float4 vA[4];
#pragma unroll
    for (int i = 0; i < 4; i++) {
        int e4 = tid + i * 256;
        int m  = e4 >> 3, kq = e4 & 7;
        vA[i] = *(const float4*)&g_h[(size_t)(row0 + m) * 128 + kq * 4];
    }

    // ---- prefetch B fragments for ks = 0 ----
    uint4 bcur[4];
#pragma unroll
    for (int p = 0; p < 4; p++)
        bcur[p] = Bf[(cg * 4 + p) * 32 + lane];

#pragma unroll
    for (int q = 0; q < 4; q++) {
        uint32_t* A = sA + (q & 1) * 4096;
        // store A quarter q in fragment order (raw bits, no cvt)
#pragma unroll
        for (int i = 0; i < 4; i++) {
            int e4 = tid + i * 256;
            int m  = e4 >> 3, kq = e4 & 7;
            int ksl  = kq >> 1;
            int kin0 = (kq & 1) * 4;
            int r = m & 15, mtile = m >> 4, gd = r & 7;
            int jb = (r >= 8 ? 1 : 0) + (kin0 ? 2 : 0);
            int b4 = (ksl * 8 + mtile) * 32 + gd * 4;
            float vv[4] = {vA[i].x, vA[i].y, vA[i].z, vA[i].w};
#pragma unroll
            for (int c = 0; c < 4; c++)
                A[(((b4 + c) ^ (ksl & 3)) << 2) + jb] = __float_as_uint(vv[c]);
        }
        __syncthreads();

        // prefetch next A quarter during compute
        if (q < 3) {
#pragma unroll
            for (int i = 0; i < 4; i++) {
                int e4 = tid + i * 256;
                int m  = e4 >> 3, kq = e4 & 7;
                vA[i] = *(const float4*)&g_h[(size_t)(row0 + m) * 128 + (q + 1) * 32 + kq * 4];
            }
        }

#pragma unroll
        for (int ksl = 0; ksl < 4; ksl++) {
            int ks = q * 4 + ksl;
            uint4 a0 = ((const uint4*)A)[((ksl * 8 + rg * 2 + 0) * 32 + lane) ^ (ksl & 3)];
            uint4 a1 = ((const uint4*)A)[((ksl * 8 + rg * 2 + 1) * 32 + lane) ^ (ksl & 3)];
            // prefetch B for next ks
            uint4 bn[4];
            if (ks < 15) {
#pragma unroll
                for (int p = 0; p < 4; p++)
                    bn[p] = Bf[((ks + 1) * 8 + cg * 4 + p) * 32 + lane];
            }
#pragma unroll
            for (int p = 0; p < 4; p++) {
                uint32_t b0[2] = {bcur[p].x, bcur[p].y};
                uint32_t b1[2] = {bcur[p].z, bcur[p].w};
                mma_tf32(acc[0][2 * p],     (const uint32_t*)&a0, b0);
                mma_tf32(acc[0][2 * p + 1], (const uint32_t*)&a0, b1);
                mma_tf32(acc[1][2 * p],     (const uint32_t*)&a1, b0);
                mma_tf32(acc[1][2 * p + 1], (const uint32_t*)&a1, b1);
            }
            if (ks < 15) {
#pragma unroll
                for (int p = 0; p < 4; p++) bcur[p] = bn[p];
            }
        }
        __syncthreads();
    }

    // ---- epilogue: bias + store (q/xr fp32, k/v bf16) ----
    bool isf32 = (mat == 0 || mat == 3);
    int off = (mat == 0 || mat == 1) ? 0 : 128;
#pragma unroll
    for (int nt = 0; nt < 8; nt++) {
        int c = cg * 64 + nt * 8 + tig * 2;
        float b0 = bias[c], b1 = bias[c + 1];
#pragma unroll
        for (int rt = 0; rt < 2; rt++) {
            int r = row0 + rg * 32 + rt * 16 + gid;
            float v00 = acc[rt][nt][0] + b0, v01 = acc[rt][nt][1] + b1;
            float v10 = acc[rt][nt][2] + b0, v11 = acc[rt][nt][3] + b1;
            if (isf32) {
                *(float2*)(g_qkvs + (size_t)r * 256 + off + c)       = make_float2(v00, v01);
                *(float2*)(g_qkvs + (size_t)(r + 8) * 256 + off + c) = make_float2(v10, v11);
            } else {
                *(__nv_bfloat162*)(g_kv + (size_t)r * 256 + off + c)       = __floats2bfloat162_rn(v00, v01);
                *(__nv_bfloat162*)(g_kv + (size_t)(r + 8) * 256 + off + c) = __floats2bfloat162_rn(v10, v11);
            }
        }
    }
}

// =====================================================================
// Fused attention: one warp per dst node, bf16 k/v. (unchanged round 5)
// =====================================================================
__global__ __launch_bounds__(256) void k_attn(
    const float* __restrict__ Wb, const float* __restrict__ bb,
    const float* __restrict__ lng, const float* __restrict__ lnb)
{
    int gw = (blockIdx.x * 256 + threadIdx.x) >> 5;   // node id
    if (gw >= NND) return;
    int lane = threadIdx.x & 31;
    int t  = lane & 15;
    int eq = lane >> 4;
    int d0 = t * 8;

    const float* qrow = g_qkvs + (size_t)gw * 256;
    float q[8];
    {
        float4 qa = ((const float4*)qrow)[t * 2];
        float4 qb = ((const float4*)qrow)[t * 2 + 1];
        q[0] = qa.x * .25f; q[1] = qa.y * .25f; q[2] = qa.z * .25f; q[3] = qa.w * .25f;
        q[4] = qb.x * .25f; q[5] = qb.y * .25f; q[6] = qb.z * .25f; q[7] = qb.w * .25f;
    }

    float acc[8] = {0.f, 0.f, 0.f, 0.f, 0.f, 0.f, 0.f, 0.f};
    float den = 0.f;

    int beg = g_off[gw], end = g_off[gw + 1];
    for (int base = beg; base < end; base += 32) {
        int cnt = min(32, end - base);
        int id = (base + lane < end) ? g_csr[base + lane] : 0;
#pragma unroll 2
        for (int e = 0; e < cnt; e += 2) {
            int ee = e + eq;
            bool act = ee < cnt;
            int s = __shfl_sync(0xffffffffu, id, ee & 31);
            const uint4* kvrow = (const uint4*)(g_kv + (size_t)s * 256);
            uint4 kr = kvrow[t];
            uint4 vr = kvrow[16 + t];
            float2 k0 = __bfloat1622float2(*(const __nv_bfloat162*)&kr.x);
            float2 k1 = __bfloat1622float2(*(const __nv_bfloat162*)&kr.y);
            float2 k2 = __bfloat1622float2(*(const __nv_bfloat162*)&kr.z);
            float2 k3 = __bfloat1622float2(*(const __nv_bfloat162*)&kr.w);
            float d = q[0] * k0.x + q[1] * k0.y + q[2] * k1.x + q[3] * k1.y
                    + q[4] * k2.x + q[5] * k2.y + q[6] * k3.x + q[7] * k3.y;
            d += __shfl_xor_sync(0xffffffffu, d, 1);   // full head score
            float p = act ? __expf(d) : 0.f;
            float2 v0 = __bfloat1622float2(*(const __nv_bfloat162*)&vr.x);
            float2 v1 = __bfloat1622float2(*(const __nv_bfloat162*)&vr.y);
            float2 v2 = __bfloat1622float2(*(const __nv_bfloat162*)&vr.z);
            float2 v3 = __bfloat1622float2(*(const __nv_bfloat162*)&vr.w);
            acc[0] += p * v0.x; acc[1] += p * v0.y;
            acc[2] += p * v1.x; acc[3] += p * v1.y;
            acc[4] += p * v2.x; acc[5] += p * v2.y;
            acc[6] += p * v3.x; acc[7] += p * v3.y;
            den += p;
        }
    }

#pragma unroll
    for (int j = 0; j < 8; j++)
        acc[j] += __shfl_xor_sync(0xffffffffu, acc[j], 16);
    den += __shfl_xor_sync(0xffffffffu, den, 16);

    float inv = 1.f / (den + 1e-16f);
    float ag[8];
#pragma unroll
    for (int j = 0; j < 8; j++) ag[j] = acc[j] * inv;

    float xr[8];
    {
        float4 xa = ((const float4*)(qrow + 128))[t * 2];
        float4 xb = ((const float4*)(qrow + 128))[t * 2 + 1];
        xr[0] = xa.x; xr[1] = xa.y; xr[2] = xa.z; xr[3] = xa.w;
        xr[4] = xb.x; xr[5] = xb.y; xr[6] = xb.z; xr[7] = xb.w;
    }

    float part = 0.f;
#pragma unroll
    for (int j = 0; j < 8; j++) {
        int d = d0 + j;
        part += ag[j] * Wb[d] + xr[j] * Wb[128 + d] + (ag[j] - xr[j]) * Wb[256 + d];
    }
#pragma unroll
    for (int o = 16; o; o >>= 1) part += __shfl_xor_sync(0xffffffffu, part, o);
    float beta = 1.f / (1.f + __expf(-(0.5f * part + bb[0])));

    float hv[8];
    {
        float4 ha = ((const float4*)(g_h + (size_t)gw * 128))[t * 2];
        float4 hb = ((const float4*)(g_h + (size_t)gw * 128))[t * 2 + 1];
        hv[0] = ha.x; hv[1] = ha.y; hv[2] = ha.z; hv[3] = ha.w;
        hv[4] = hb.x; hv[5] = hb.y; hv[6] = hb.z; hv[7] = hb.w;
    }
    float y[8];
#pragma unroll
    for (int j = 0; j < 8; j++)
        y[j] = hv[j] + beta * xr[j] + (1.f - beta) * ag[j];

    float ssum = 0.f;
#pragma unroll
    for (int j = 0; j < 8; j++) ssum += y[j];
#pragma unroll
    for (int o = 16; o; o >>= 1) ssum += __shfl_xor_sync(0xffffffffu, ssum, o);
    float mean = ssum * (1.f / 256.f);

    float vs = 0.f;
#pragma unroll
    for (int j = 0; j < 8; j++) { float tv = y[j] - mean; vs += tv * tv; }
#pragma unroll
    for (int o = 16; o; o >>= 1) vs += __shfl_xor_sync(0xffffffffu, vs, o);
    float rstd = rsqrtf(vs * (1.f / 256.f) + 1e-5f);

    if (eq == 0) {
        float4 oA, oB;
        oA.x = (y[0] - mean) * rstd * lng[d0 + 0] + lnb[d0 + 0];
        oA.y = (y[1] - mean) * rstd * lng[d0 + 1] + lnb[d0 + 1];
        oA.z = (y[2] - mean) * rstd * lng[d0 + 2] + lnb[d0 + 2];
        oA.w = (y[3] - mean) * rstd * lng[d0 + 3] + lnb[d0 + 3];
        oB.x = (y[4] - mean) * rstd * lng[d0 + 4] + lnb[d0 + 4];
        oB.y = (y[5] - mean) * rstd * lng[d0 + 5] + lnb[d0 + 5];
        oB.z = (y[6] - mean) * rstd * lng[d0 + 6] + lnb[d0 + 6];
        oB.w = (y[7] - mean) * rstd * lng[d0 + 7] + lnb[d0 + 7];
        ((float4*)(g_h + (size_t)gw * 128))[t * 2]     = oA;
        ((float4*)(g_h + (size_t)gw * 128))[t * 2 + 1] = oB;
    }
}

// =====================================================================
// Output head: out = relu(h @ Wo1 + bo1) @ Wo2 + bo2    (16 nodes / block)
// =====================================================================
__global__ __launch_bounds__(256) void k_out(
    const float* __restrict__ Wo1, const float* __restrict__ bo1,
    const float* __restrict__ Wo2, const float* __restrict__ bo2,
    float* __restrict__ out)
{
    __shared__ float w1[128 * 64];
    __shared__ float hs[16][128];
    __shared__ float ts[16][64];
    int tid = threadIdx.x;
    int n0 = blockIdx.x * 16;

    for (int i = tid; i < 128 * 64 / 4; i += 256)
        ((float4*)w1)[i] = ((const float4*)Wo1)[i];
    for (int i = tid; i < 16 * 128 / 4; i += 256)
        ((float4*)&hs[0][0])[i] = ((const float4*)(g_h + (size_t)n0 * 128))[i];
    __syncthreads();

    int j = tid & 63, g0 = tid >> 6;
    float a0 = bo1[j], a1 = a0, a2 = a0, a3 = a0;
#pragma unroll 8
    for (int d = 0; d < 128; d++) {
        float w = w1[d * 64 + j];
        a0 = fmaf(hs[g0 +  0][d], w, a0);
        a1 = fmaf(hs[g0 +  4][d], w, a1);
        a2 = fmaf(hs[g0 +  8][d], w, a2);
        a3 = fmaf(hs[g0 + 12][d], w, a3);
    }
    ts[g0 +  0][j] = fmaxf(a0, 0.f);
    ts[g0 +  4][j] = fmaxf(a1, 0.f);
    ts[g0 +  8][j] = fmaxf(a2, 0.f);
    ts[g0 + 12][j] = fmaxf(a3, 0.f);
    __syncthreads();

    if (tid < 48) {
        int n = tid / 3, c = tid % 3;
        float o = bo2[c];
#pragma unroll
        for (int k = 0; k < 64; k++) o = fmaf(ts[n][k], Wo2[k * 3 + c], o);
        out[(size_t)(n0 + n) * 3 + c] = o;
    }
}

// =====================================================================
// launcher  (k_gemm layer0 kept in the ncu-captured 4th slot:
//            k_prep, k_count, k_input, k_gemm, ...)
// =====================================================================
extern "C" void kernel_launch(void* const* d_in, const int* in_sizes, int n_in,
                              void* d_out, int out_size)
{
    const float* x    = (const float*)d_in[0];
    const int*   ei   = (const int*)  d_in[1];
    const float* pe   = (const float*)d_in[2];
    const float* Win  = (const float*)d_in[3];
    const float* bin  = (const float*)d_in[4];
    const float* Wq   = (const float*)d_in[5];
    const float* bq   = (const float*)d_in[6];
    const float* Wk   = (const float*)d_in[7];
    const float* bk   = (const float*)d_in[8];
    const float* Wv   = (const float*)d_in[9];
    const float* bv   = (const float*)d_in[10];
    const float* Ws   = (const float*)d_in[11];
    const float* bs   = (const float*)d_in[12];
    const float* Wb   = (const float*)d_in[13];
    const float* bb   = (const float*)d_in[14];
    const float* lng  = (const float*)d_in[15];
    const float* lnb  = (const float*)d_in[16];
    const float* Wo1  = (const float*)d_in[17];
    const float* bo1  = (const float*)d_in[18];
    const float* Wo2  = (const float*)d_in[19];
    const float* bo2  = (const float*)d_in[20];
    float* out = (float*)d_out;

    const int* src = ei;
    const int* dst = ei + EDG;

    // 1: weight preconversion + g_deg zero
    k_prep<<<28, 256>>>(Wq, Wk, Wv, Ws);
    // 2-3
    k_count<<<EDG / 256, 256>>>(dst);
    k_input<<<NND * DD / 256, 256>>>(x, Win, bin, pe);

    // 4: layer-0 GEMM (profiled slot)
    dim3 gg(NND / 128, 4);
    k_gemm<<<gg, 256>>>(0, bq, bk, bv, bs);

    k_scan<<<1, 512>>>();
    k_fill<<<EDG / 256, 256>>>(src, dst);

    k_attn<<<NND / 8, 256>>>(Wb, bb, lng, lnb);
    for (int l = 1; l < LL; l++) {
        k_gemm<<<gg, 256>>>(l, bq + l * DD, bk + l * DD, bv + l * DD, bs + l * DD);
        k_attn<<<NND / 8, 256>>>(Wb + l * 384, bb + l, lng + l * DD, lnb + l * DD);
    }

    k_out<<<NND / 16, 256>>>(Wo1, bo1, Wo2, bo2, out);
}